// round 3
// baseline (speedup 1.0000x reference)
#include <cuda_runtime.h>

#define HS 16

// ---- fast near-exact activations ----
__device__ __forceinline__ float ex2a(float x) { float r; asm("ex2.approx.f32 %0, %1;" : "=f"(r) : "f"(x)); return r; }
__device__ __forceinline__ float rcpa(float x) { float r; asm("rcp.approx.f32 %0, %1;" : "=f"(r) : "f"(x)); return r; }
__device__ __forceinline__ float sigf(float x) { return rcpa(1.0f + ex2a(x * -1.4426950408889634f)); }
__device__ __forceinline__ float tnhf(float x) { return fmaf(2.0f, rcpa(1.0f + ex2a(x * -2.8853900817779268f)), -1.0f); }

__global__ void __launch_bounds__(128, 2) infect_lstm_kernel(
    const float* __restrict__ mob,   // [B,7]
    const float* __restrict__ ctrl,  // [B,5]
    const float* __restrict__ Wcc,   // [3,5]
    const float* __restrict__ bcc,   // [3]
    const float* __restrict__ Wih,   // [64,1]
    const float* __restrict__ Whh,   // [64,16]
    const float* __restrict__ bih,   // [64]
    const float* __restrict__ bhh,   // [64]
    const float* __restrict__ W1,    // [16,19]
    const float* __restrict__ b1,    // [16]
    const float* __restrict__ W2,    // [16,16]
    const float* __restrict__ b2,    // [16]
    const float* __restrict__ W3,    // [1,16]
    const float* __restrict__ b3,    // [1]
    float* __restrict__ out,         // [B]
    int halfB)
{
    __shared__ __align__(16) float4 sWhh[HS * HS];   // [k][m] -> (i,f,g,o)
    __shared__ __align__(16) float4 sWih[HS];        // [k]    -> (i,f,g,o)
    __shared__ __align__(16) float4 sBias[HS];       // [k]    -> b_ih+b_hh
    __shared__ float sW1[16 * 19];
    __shared__ float sB1[16];
    __shared__ float sW2[16 * 16];
    __shared__ float sB2[16];
    __shared__ float sW3[16];
    __shared__ float sWcc[3 * 5];
    __shared__ float sBcc[3];
    __shared__ float sB3;

    const int tid = threadIdx.x;

    for (int i = tid; i < HS * HS; i += 128) {
        int m = i & 15, k = i >> 4;
        sWhh[i] = make_float4(Whh[(0 * 16 + k) * 16 + m],
                              Whh[(1 * 16 + k) * 16 + m],
                              Whh[(2 * 16 + k) * 16 + m],
                              Whh[(3 * 16 + k) * 16 + m]);
    }
    if (tid < HS) {
        int k = tid;
        sWih[k]  = make_float4(Wih[k], Wih[16 + k], Wih[32 + k], Wih[48 + k]);
        sBias[k] = make_float4(bih[k]      + bhh[k],
                               bih[16 + k] + bhh[16 + k],
                               bih[32 + k] + bhh[32 + k],
                               bih[48 + k] + bhh[48 + k]);
    }
    for (int i = tid; i < 16 * 19; i += 128) sW1[i] = W1[i];
    for (int i = tid; i < 16 * 16; i += 128) sW2[i] = W2[i];
    if (tid < 16) sB1[tid] = b1[tid];
    else if (tid < 32) sB2[tid - 16] = b2[tid - 16];
    else if (tid < 48) sW3[tid - 32] = W3[tid - 32];
    else if (tid < 63) sWcc[tid - 48] = Wcc[tid - 48];
    else if (tid < 66) sBcc[tid - 63] = bcc[tid - 63];
    else if (tid == 66) sB3 = b3[0];
    __syncthreads();

    const int e0 = blockIdx.x * 128 + tid;   // element A
    const int e1 = e0 + halfB;               // element B
    const float* mpA = mob + (size_t)e0 * 7;
    const float* mpB = mob + (size_t)e1 * 7;
    const float* cpA = ctrl + (size_t)e0 * 5;
    const float* cpB = ctrl + (size_t)e1 * 5;

    float xmA[7], xmB[7];
#pragma unroll
    for (int s = 0; s < 7; s++) { xmA[s] = mpA[s]; xmB[s] = mpB[s]; }

    // ---- control head: Linear(5->3), both elements ----
    float ctlA[3], ctlB[3];
    {
        float ca[5], cb[5];
#pragma unroll
        for (int i = 0; i < 5; i++) { ca[i] = cpA[i]; cb[i] = cpB[i]; }
#pragma unroll
        for (int j = 0; j < 3; j++) {
            float aA = sBcc[j], aB = aA;
#pragma unroll
            for (int i = 0; i < 5; i++) {
                float w = sWcc[j * 5 + i];
                aA = fmaf(ca[i], w, aA);
                aB = fmaf(cb[i], w, aB);
            }
            ctlA[j] = aA; ctlB[j] = aB;
        }
    }

    // ---- LSTM: 7 steps, H=16, 2 elements ----
    float hA[HS], cA[HS], hB[HS], cB[HS];
#pragma unroll
    for (int k = 0; k < HS; k++) { hA[k] = 0.f; cA[k] = 0.f; hB[k] = 0.f; cB[k] = 0.f; }

#pragma unroll 1
    for (int s = 0; s < 7; s++) {
        const float xA = xmA[s], xB = xmB[s];
        float hnA[HS], hnB[HS];
#pragma unroll
        for (int k = 0; k < HS; k++) {
            float4 wx = sWih[k];
            float4 bb = sBias[k];
            float aiA = fmaf(xA, wx.x, bb.x), aiB = fmaf(xB, wx.x, bb.x);
            float afA = fmaf(xA, wx.y, bb.y), afB = fmaf(xB, wx.y, bb.y);
            float agA = fmaf(xA, wx.z, bb.z), agB = fmaf(xB, wx.z, bb.z);
            float aoA = fmaf(xA, wx.w, bb.w), aoB = fmaf(xB, wx.w, bb.w);
#pragma unroll
            for (int m = 0; m < HS; m++) {
                float4 w = sWhh[k * HS + m];
                float ha = hA[m], hb = hB[m];
                aiA = fmaf(ha, w.x, aiA);  aiB = fmaf(hb, w.x, aiB);
                afA = fmaf(ha, w.y, afA);  afB = fmaf(hb, w.y, afB);
                agA = fmaf(ha, w.z, agA);  agB = fmaf(hb, w.z, agB);
                aoA = fmaf(ha, w.w, aoA);  aoB = fmaf(hb, w.w, aoB);
            }
            float igA = sigf(aiA), igB = sigf(aiB);
            float fgA = sigf(afA), fgB = sigf(afB);
            float ggA = tnhf(agA), ggB = tnhf(agB);
            float ogA = sigf(aoA), ogB = sigf(aoB);
            float ckA = fmaf(fgA, cA[k], igA * ggA);
            float ckB = fmaf(fgB, cB[k], igB * ggB);
            cA[k] = ckA; cB[k] = ckB;
            hnA[k] = ogA * tnhf(ckA);
            hnB[k] = ogB * tnhf(ckB);
        }
#pragma unroll
        for (int k = 0; k < HS; k++) { hA[k] = hnA[k]; hB[k] = hnB[k]; }
    }

    // ---- FC head ----
    float x1A[16], x1B[16];
#pragma unroll
    for (int j = 0; j < 16; j++) {
        float aA = sB1[j], aB = aA;
#pragma unroll
        for (int i = 0; i < 16; i++) {
            float w = sW1[j * 19 + i];
            aA = fmaf(hA[i], w, aA);
            aB = fmaf(hB[i], w, aB);
        }
#pragma unroll
        for (int i = 0; i < 3; i++) {
            float w = sW1[j * 19 + 16 + i];
            aA = fmaf(ctlA[i], w, aA);
            aB = fmaf(ctlB[i], w, aB);
        }
        x1A[j] = tnhf(aA); x1B[j] = tnhf(aB);
    }
    float x2A[16], x2B[16];
#pragma unroll
    for (int j = 0; j < 16; j++) {
        float aA = sB2[j], aB = aA;
#pragma unroll
        for (int i = 0; i < 16; i++) {
            float w = sW2[j * 16 + i];
            aA = fmaf(x1A[i], w, aA);
            aB = fmaf(x1B[i], w, aB);
        }
        x2A[j] = tnhf(aA); x2B[j] = tnhf(aB);
    }
    float aA = sB3, aB = sB3;
#pragma unroll
    for (int i = 0; i < 16; i++) {
        float w = sW3[i];
        aA = fmaf(x2A[i], w, aA);
        aB = fmaf(x2B[i], w, aB);
    }

    out[e0] = fmaxf(aA, 0.0f);
    out[e1] = fmaxf(aB, 0.0f);
}

extern "C" void kernel_launch(void* const* d_in, const int* in_sizes, int n_in,
                              void* d_out, int out_size)
{
    const float* mob  = (const float*)d_in[0];
    const float* ctrl = (const float*)d_in[1];
    const float* Wcc  = (const float*)d_in[3];
    const float* bcc  = (const float*)d_in[4];
    const float* Wih  = (const float*)d_in[5];
    const float* Whh  = (const float*)d_in[6];
    const float* bih  = (const float*)d_in[7];
    const float* bhh  = (const float*)d_in[8];
    const float* W1   = (const float*)d_in[9];
    const float* b1   = (const float*)d_in[10];
    const float* W2   = (const float*)d_in[11];
    const float* b2   = (const float*)d_in[12];
    const float* W3   = (const float*)d_in[13];
    const float* b3   = (const float*)d_in[14];

    int B = in_sizes[2];
    int halfB = B / 2;
    int blocks = (halfB + 127) / 128;

    infect_lstm_kernel<<<blocks, 128>>>(mob, ctrl, Wcc, bcc, Wih, Whh, bih, bhh,
                                        W1, b1, W2, b2, W3, b3, (float*)d_out, halfB);
}

// round 4
// speedup vs baseline: 1.0537x; 1.0537x over previous
#include <cuda_runtime.h>

#define HS 16

// ---- fast near-exact activations ----
__device__ __forceinline__ float ex2a(float x) { float r; asm("ex2.approx.f32 %0, %1;" : "=f"(r) : "f"(x)); return r; }
__device__ __forceinline__ float rcpa(float x) { float r; asm("rcp.approx.f32 %0, %1;" : "=f"(r) : "f"(x)); return r; }
__device__ __forceinline__ float sigf(float x) { return rcpa(1.0f + ex2a(x * -1.4426950408889634f)); }
__device__ __forceinline__ float tnhf(float x) { return fmaf(2.0f, rcpa(1.0f + ex2a(x * -2.8853900817779268f)), -1.0f); }

__global__ void __launch_bounds__(128, 3) infect_lstm_kernel(
    const float* __restrict__ mob,   // [B,7]
    const float* __restrict__ ctrl,  // [B,5]
    const float* __restrict__ Wcc,   // [3,5]
    const float* __restrict__ bcc,   // [3]
    const float* __restrict__ Wih,   // [64,1]
    const float* __restrict__ Whh,   // [64,16]
    const float* __restrict__ bih,   // [64]
    const float* __restrict__ bhh,   // [64]
    const float* __restrict__ W1,    // [16,19]
    const float* __restrict__ b1,    // [16]
    const float* __restrict__ W2,    // [16,16]
    const float* __restrict__ b2,    // [16]
    const float* __restrict__ W3,    // [1,16]
    const float* __restrict__ b3,    // [1]
    float* __restrict__ out)         // [B]
{
    __shared__ __align__(16) float4 sWhh[HS * HS];   // [k][m] -> (i,f,g,o)
    __shared__ __align__(16) float4 sWih[HS];        // [k]    -> (i,f,g,o)
    __shared__ __align__(16) float4 sBias[HS];       // [k]    -> b_ih+b_hh
    __shared__ float sW1[16 * 19];
    __shared__ float sB1[16];
    __shared__ float sW2[16 * 16];
    __shared__ float sB2[16];
    __shared__ float sW3[16];
    __shared__ float sWcc[3 * 5];
    __shared__ float sBcc[3];
    __shared__ float sB3;

    const int tid = threadIdx.x;

    for (int i = tid; i < HS * HS; i += 128) {
        int m = i & 15, k = i >> 4;
        sWhh[i] = make_float4(Whh[(0 * 16 + k) * 16 + m],
                              Whh[(1 * 16 + k) * 16 + m],
                              Whh[(2 * 16 + k) * 16 + m],
                              Whh[(3 * 16 + k) * 16 + m]);
    }
    if (tid < HS) {
        int k = tid;
        sWih[k]  = make_float4(Wih[k], Wih[16 + k], Wih[32 + k], Wih[48 + k]);
        sBias[k] = make_float4(bih[k]      + bhh[k],
                               bih[16 + k] + bhh[16 + k],
                               bih[32 + k] + bhh[32 + k],
                               bih[48 + k] + bhh[48 + k]);
    }
    for (int i = tid; i < 16 * 19; i += 128) sW1[i] = W1[i];
    for (int i = tid; i < 16 * 16; i += 128) sW2[i] = W2[i];
    if (tid < 16) sB1[tid] = b1[tid];
    else if (tid < 32) sB2[tid - 16] = b2[tid - 16];
    else if (tid < 48) sW3[tid - 32] = W3[tid - 32];
    else if (tid < 63) sWcc[tid - 48] = Wcc[tid - 48];
    else if (tid < 66) sBcc[tid - 63] = bcc[tid - 63];
    else if (tid == 66) sB3 = b3[0];
    __syncthreads();

    const int t = blockIdx.x * 128 + tid;
    const float* mp = mob + (size_t)t * 7;
    const float* cp = ctrl + (size_t)t * 5;

    // ---- control head: Linear(5->3) (fully unrolled, registers only) ----
    float ctl0, ctl1, ctl2;
    {
        float c0 = cp[0], c1 = cp[1], c2 = cp[2], c3 = cp[3], c4 = cp[4];
        ctl0 = sBcc[0];
        ctl0 = fmaf(c0, sWcc[0], ctl0); ctl0 = fmaf(c1, sWcc[1], ctl0);
        ctl0 = fmaf(c2, sWcc[2], ctl0); ctl0 = fmaf(c3, sWcc[3], ctl0);
        ctl0 = fmaf(c4, sWcc[4], ctl0);
        ctl1 = sBcc[1];
        ctl1 = fmaf(c0, sWcc[5], ctl1); ctl1 = fmaf(c1, sWcc[6], ctl1);
        ctl1 = fmaf(c2, sWcc[7], ctl1); ctl1 = fmaf(c3, sWcc[8], ctl1);
        ctl1 = fmaf(c4, sWcc[9], ctl1);
        ctl2 = sBcc[2];
        ctl2 = fmaf(c0, sWcc[10], ctl2); ctl2 = fmaf(c1, sWcc[11], ctl2);
        ctl2 = fmaf(c2, sWcc[12], ctl2); ctl2 = fmaf(c3, sWcc[13], ctl2);
        ctl2 = fmaf(c4, sWcc[14], ctl2);
    }

    // ---- LSTM: 7 steps, H=16 ----
    float h[HS], c[HS];
#pragma unroll
    for (int k = 0; k < HS; k++) { h[k] = 0.0f; c[k] = 0.0f; }

#pragma unroll 1
    for (int s = 0; s < 7; s++) {
        const float x = mp[s];          // direct global load, no local array
        float hn[HS];
#pragma unroll
        for (int k = 0; k < HS; k++) {
            float4 wx = sWih[k];
            float4 bb = sBias[k];
            float ai = fmaf(x, wx.x, bb.x);
            float af = fmaf(x, wx.y, bb.y);
            float ag = fmaf(x, wx.z, bb.z);
            float ao = fmaf(x, wx.w, bb.w);
#pragma unroll
            for (int m = 0; m < HS; m++) {
                float4 w = sWhh[k * HS + m];
                float hm = h[m];
                ai = fmaf(hm, w.x, ai);
                af = fmaf(hm, w.y, af);
                ag = fmaf(hm, w.z, ag);
                ao = fmaf(hm, w.w, ao);
            }
            float ig = sigf(ai);
            float fg = sigf(af);
            float gg = tnhf(ag);
            float og = sigf(ao);
            float ck = fmaf(fg, c[k], ig * gg);
            c[k] = ck;
            hn[k] = og * tnhf(ck);
        }
#pragma unroll
        for (int k = 0; k < HS; k++) h[k] = hn[k];
    }

    // ---- FC head: (19->16) tanh, (16->16) tanh, (16->1) relu ----
    float x1[16];
#pragma unroll
    for (int j = 0; j < 16; j++) {
        float acc = sB1[j];
#pragma unroll
        for (int i = 0; i < 16; i++) acc = fmaf(h[i], sW1[j * 19 + i], acc);
        acc = fmaf(ctl0, sW1[j * 19 + 16], acc);
        acc = fmaf(ctl1, sW1[j * 19 + 17], acc);
        acc = fmaf(ctl2, sW1[j * 19 + 18], acc);
        x1[j] = tnhf(acc);
    }
    float x2[16];
#pragma unroll
    for (int j = 0; j < 16; j++) {
        float acc = sB2[j];
#pragma unroll
        for (int i = 0; i < 16; i++) acc = fmaf(x1[i], sW2[j * 16 + i], acc);
        x2[j] = tnhf(acc);
    }
    float acc = sB3;
#pragma unroll
    for (int i = 0; i < 16; i++) acc = fmaf(x2[i], sW3[i], acc);

    out[t] = fmaxf(acc, 0.0f);
}

extern "C" void kernel_launch(void* const* d_in, const int* in_sizes, int n_in,
                              void* d_out, int out_size)
{
    const float* mob  = (const float*)d_in[0];
    const float* ctrl = (const float*)d_in[1];
    const float* Wcc  = (const float*)d_in[3];
    const float* bcc  = (const float*)d_in[4];
    const float* Wih  = (const float*)d_in[5];
    const float* Whh  = (const float*)d_in[6];
    const float* bih  = (const float*)d_in[7];
    const float* bhh  = (const float*)d_in[8];
    const float* W1   = (const float*)d_in[9];
    const float* b1   = (const float*)d_in[10];
    const float* W2   = (const float*)d_in[11];
    const float* b2   = (const float*)d_in[12];
    const float* W3   = (const float*)d_in[13];
    const float* b3   = (const float*)d_in[14];

    int B = in_sizes[2];
    int blocks = (B + 127) / 128;

    infect_lstm_kernel<<<blocks, 128>>>(mob, ctrl, Wcc, bcc, Wih, Whh, bih, bhh,
                                        W1, b1, W2, b2, W3, b3, (float*)d_out);
}

// round 6
// speedup vs baseline: 4.5364x; 4.3054x over previous
#include <cuda_runtime.h>

// ---- fast near-exact activations ----
__device__ __forceinline__ float ex2a(float x) { float r; asm("ex2.approx.f32 %0, %1;" : "=f"(r) : "f"(x)); return r; }
__device__ __forceinline__ float rcpa(float x) { float r; asm("rcp.approx.f32 %0, %1;" : "=f"(r) : "f"(x)); return r; }
__device__ __forceinline__ float sigf(float x) { return rcpa(1.0f + ex2a(x * -1.4426950408889634f)); }
__device__ __forceinline__ float tnhf(float x) { return fmaf(2.0f, rcpa(1.0f + ex2a(x * -2.8853900817779268f)), -1.0f); }

// Block = 256 threads = 8 warps; each warp handles 2 elements (16 lanes each).
// Lane u (0..15 within half-warp) owns hidden unit u: scalar h, c.
__global__ void __launch_bounds__(256, 4) infect_lstm_kernel(
    const float* __restrict__ mob,   // [B,7]
    const float* __restrict__ ctrl,  // [B,5]
    const float* __restrict__ Wcc,   // [3,5]
    const float* __restrict__ bcc,   // [3]
    const float* __restrict__ Wih,   // [64,1]
    const float* __restrict__ Whh,   // [64,16]
    const float* __restrict__ bih,   // [64]
    const float* __restrict__ bhh,   // [64]
    const float* __restrict__ W1,    // [16,19]
    const float* __restrict__ b1,    // [16]
    const float* __restrict__ W2,    // [16,16]
    const float* __restrict__ b2,    // [16]
    const float* __restrict__ W3,    // [1,16]
    const float* __restrict__ b3,    // [1]
    float* __restrict__ out)         // [B]
{
    // Transposed weight layouts: index [m][u] so 16 lanes read 16 consecutive
    // entries -> conflict-free broadcastable LDS.
    __shared__ __align__(16) float4 sWhhT[16 * 16]; // [m][u] -> (wi,wf,wg,wo)
    __shared__ __align__(16) float4 sWxB[16];       // [u] -> Wih per gate
    __shared__ __align__(16) float4 sBiasV[16];     // [u] -> bih+bhh per gate
    __shared__ float sW1T[19 * 16];                 // [i][u] = W1[u][i]
    __shared__ float sW2T[16 * 16];                 // [i][u] = W2[u][i]
    __shared__ float sW3[16], sB1[16], sB2[16];
    __shared__ float sWcc[15], sBcc[3], sB3[1];

    const int tid = threadIdx.x;

    {   // one entry per thread
        int m = tid >> 4, u = tid & 15;
        sWhhT[tid] = make_float4(Whh[u * 16 + m],
                                 Whh[(16 + u) * 16 + m],
                                 Whh[(32 + u) * 16 + m],
                                 Whh[(48 + u) * 16 + m]);
        sW2T[tid] = W2[u * 16 + m];   // [i=m][u]
    }
    for (int i = tid; i < 19 * 16; i += 256) {
        int col = i >> 4, u = i & 15;
        sW1T[i] = W1[u * 19 + col];
    }
    if (tid < 16) {
        int u = tid;
        sWxB[u]   = make_float4(Wih[u], Wih[16 + u], Wih[32 + u], Wih[48 + u]);
        sBiasV[u] = make_float4(bih[u]      + bhh[u],
                                bih[16 + u] + bhh[16 + u],
                                bih[32 + u] + bhh[32 + u],
                                bih[48 + u] + bhh[48 + u]);
        sW3[u] = W3[u]; sB1[u] = b1[u]; sB2[u] = b2[u];
    } else if (tid < 31) sWcc[tid - 16] = Wcc[tid - 16];
    else if (tid < 34) sBcc[tid - 31] = bcc[tid - 31];
    else if (tid == 34) sB3[0] = b3[0];
    __syncthreads();

    const int lane = tid & 31;
    const int u = lane & 15;
    const int gwarp = blockIdx.x * 8 + (tid >> 5);
    const int elem = gwarp * 2 + (lane >> 4);

    const float* mp = mob + (size_t)elem * 7;
    const float* cp = ctrl + (size_t)elem * 5;

    // ---- control head: every lane computes its element's 3 ctl values ----
    float ctl0 = sBcc[0], ctl1 = sBcc[1], ctl2 = sBcc[2];
#pragma unroll
    for (int i = 0; i < 5; i++) {
        float cv = cp[i];                    // same addr across half-warp -> broadcast
        ctl0 = fmaf(cv, sWcc[i],      ctl0);
        ctl1 = fmaf(cv, sWcc[5 + i],  ctl1);
        ctl2 = fmaf(cv, sWcc[10 + i], ctl2);
    }

    // ---- LSTM: 7 steps; lane u owns unit u ----
    const float4 wx = sWxB[u];
    const float4 bb = sBiasV[u];
    float h = 0.0f, c = 0.0f;

#pragma unroll 1
    for (int s = 0; s < 7; s++) {
        const float x = mp[s];
        float ai = fmaf(x, wx.x, bb.x);
        float af = fmaf(x, wx.y, bb.y);
        float ag = fmaf(x, wx.z, bb.z);
        float ao = fmaf(x, wx.w, bb.w);
#pragma unroll
        for (int m = 0; m < 16; m++) {
            float hm = __shfl_sync(0xffffffffu, h, m, 16);  // broadcast within 16-lane group
            float4 w = sWhhT[m * 16 + u];
            ai = fmaf(hm, w.x, ai);
            af = fmaf(hm, w.y, af);
            ag = fmaf(hm, w.z, ag);
            ao = fmaf(hm, w.w, ao);
        }
        float ig = sigf(ai);
        float fg = sigf(af);
        float gg = tnhf(ag);
        float og = sigf(ao);
        c = fmaf(fg, c, ig * gg);
        h = og * tnhf(c);
    }

    // ---- FC1: 19->16, tanh ----
    float a1 = sB1[u];
#pragma unroll
    for (int i = 0; i < 16; i++)
        a1 = fmaf(__shfl_sync(0xffffffffu, h, i, 16), sW1T[i * 16 + u], a1);
    a1 = fmaf(ctl0, sW1T[16 * 16 + u], a1);
    a1 = fmaf(ctl1, sW1T[17 * 16 + u], a1);
    a1 = fmaf(ctl2, sW1T[18 * 16 + u], a1);
    float x1 = tnhf(a1);

    // ---- FC2: 16->16, tanh ----
    float a2 = sB2[u];
#pragma unroll
    for (int i = 0; i < 16; i++)
        a2 = fmaf(__shfl_sync(0xffffffffu, x1, i, 16), sW2T[i * 16 + u], a2);
    float x2 = tnhf(a2);

    // ---- FC3: 16->1, relu; butterfly reduction over the 16-lane group ----
    float p = x2 * sW3[u];
#pragma unroll
    for (int off = 8; off; off >>= 1)
        p += __shfl_xor_sync(0xffffffffu, p, off, 16);

    if (u == 0) out[elem] = fmaxf(p + sB3[0], 0.0f);
}

extern "C" void kernel_launch(void* const* d_in, const int* in_sizes, int n_in,
                              void* d_out, int out_size)
{
    const float* mob  = (const float*)d_in[0];
    const float* ctrl = (const float*)d_in[1];
    const float* Wcc  = (const float*)d_in[3];
    const float* bcc  = (const float*)d_in[4];
    const float* Wih  = (const float*)d_in[5];
    const float* Whh  = (const float*)d_in[6];
    const float* bih  = (const float*)d_in[7];
    const float* bhh  = (const float*)d_in[8];
    const float* W1   = (const float*)d_in[9];
    const float* b1   = (const float*)d_in[10];
    const float* W2   = (const float*)d_in[11];
    const float* b2   = (const float*)d_in[12];
    const float* W3   = (const float*)d_in[13];
    const float* b3   = (const float*)d_in[14];

    int B = in_sizes[2];
    int blocks = (B + 15) / 16;     // 16 elements per 256-thread block

    infect_lstm_kernel<<<blocks, 256>>>(mob, ctrl, Wcc, bcc, Wih, Whh, bih, bhh,
                                        W1, b1, W2, b2, W3, b3, (float*)d_out);
}

// round 7
// speedup vs baseline: 7.4523x; 1.6428x over previous
#include <cuda_runtime.h>

// ---- fast near-exact activations ----
__device__ __forceinline__ float ex2a(float x) { float r; asm("ex2.approx.f32 %0, %1;" : "=f"(r) : "f"(x)); return r; }
__device__ __forceinline__ float rcpa(float x) { float r; asm("rcp.approx.f32 %0, %1;" : "=f"(r) : "f"(x)); return r; }
__device__ __forceinline__ float sigf(float x) { return rcpa(1.0f + ex2a(x * -1.4426950408889634f)); }
__device__ __forceinline__ float tnhf(float x) { return fmaf(2.0f, rcpa(1.0f + ex2a(x * -2.8853900817779268f)), -1.0f); }

// Block = 256 threads = 8 warps; each warp handles 2 elements (16 lanes each).
// Lane u owns hidden unit u. Whh weights live in registers for the hot loop.
__global__ void __launch_bounds__(256, 2) infect_lstm_kernel(
    const float* __restrict__ mob,   // [B,7]
    const float* __restrict__ ctrl,  // [B,5]
    const float* __restrict__ Wcc,   // [3,5]
    const float* __restrict__ bcc,   // [3]
    const float* __restrict__ Wih,   // [64,1]
    const float* __restrict__ Whh,   // [64,16]
    const float* __restrict__ bih,   // [64]
    const float* __restrict__ bhh,   // [64]
    const float* __restrict__ W1,    // [16,19]
    const float* __restrict__ b1,    // [16]
    const float* __restrict__ W2,    // [16,16]
    const float* __restrict__ b2,    // [16]
    const float* __restrict__ W3,    // [1,16]
    const float* __restrict__ b3,    // [1]
    float* __restrict__ out)         // [B]
{
    __shared__ __align__(16) float4 sWhhT[16 * 16]; // [m][u] -> (wi,wf,wg,wo)
    __shared__ __align__(16) float4 sWxB[16];       // [u] -> Wih per gate
    __shared__ __align__(16) float4 sBiasV[16];     // [u] -> bih+bhh per gate
    __shared__ float sW1T[19 * 16];                 // [i][u] = W1[u][i]
    __shared__ float sW2T[16 * 16];                 // [i][u] = W2[u][i]
    __shared__ float sW3[16], sB1[16], sB2[16];
    __shared__ float sWcc[15], sBcc[3], sB3[1];

    const int tid = threadIdx.x;

    {   // one entry per thread
        int m = tid >> 4, uu = tid & 15;
        sWhhT[tid] = make_float4(Whh[uu * 16 + m],
                                 Whh[(16 + uu) * 16 + m],
                                 Whh[(32 + uu) * 16 + m],
                                 Whh[(48 + uu) * 16 + m]);
        sW2T[tid] = W2[uu * 16 + m];   // [i=m][u]
    }
    for (int i = tid; i < 19 * 16; i += 256) {
        int col = i >> 4, uu = i & 15;
        sW1T[i] = W1[uu * 19 + col];
    }
    if (tid < 16) {
        int uu = tid;
        sWxB[uu]   = make_float4(Wih[uu], Wih[16 + uu], Wih[32 + uu], Wih[48 + uu]);
        sBiasV[uu] = make_float4(bih[uu]      + bhh[uu],
                                 bih[16 + uu] + bhh[16 + uu],
                                 bih[32 + uu] + bhh[32 + uu],
                                 bih[48 + uu] + bhh[48 + uu]);
        sW3[uu] = W3[uu]; sB1[uu] = b1[uu]; sB2[uu] = b2[uu];
    } else if (tid < 31) sWcc[tid - 16] = Wcc[tid - 16];
    else if (tid < 34) sBcc[tid - 31] = bcc[tid - 31];
    else if (tid == 34) sB3[0] = b3[0];
    __syncthreads();

    const int lane = tid & 31;
    const int u = lane & 15;
    const int gwarp = blockIdx.x * 8 + (tid >> 5);
    const int elem = gwarp * 2 + (lane >> 4);

    const float* mp = mob + (size_t)elem * 7;
    const float* cp = ctrl + (size_t)elem * 5;

    // ---- control head ----
    float ctl0 = sBcc[0], ctl1 = sBcc[1], ctl2 = sBcc[2];
#pragma unroll
    for (int i = 0; i < 5; i++) {
        float cv = cp[i];
        ctl0 = fmaf(cv, sWcc[i],      ctl0);
        ctl1 = fmaf(cv, sWcc[5 + i],  ctl1);
        ctl2 = fmaf(cv, sWcc[10 + i], ctl2);
    }

    // ---- hoist this lane's Whh column set into registers (64 regs) ----
    float4 wreg[16];
#pragma unroll
    for (int m = 0; m < 16; m++) wreg[m] = sWhhT[m * 16 + u];

    const float4 wx = sWxB[u];
    const float4 bb = sBiasV[u];
    float h = 0.0f, c = 0.0f;

    // ---- LSTM: 7 steps; zero LDS inside ----
#pragma unroll 1
    for (int s = 0; s < 7; s++) {
        const float x = mp[s];
        float ai = fmaf(x, wx.x, bb.x);
        float af = fmaf(x, wx.y, bb.y);
        float ag = fmaf(x, wx.z, bb.z);
        float ao = fmaf(x, wx.w, bb.w);
#pragma unroll
        for (int m = 0; m < 16; m++) {
            float hm = __shfl_sync(0xffffffffu, h, m, 16);
            ai = fmaf(hm, wreg[m].x, ai);
            af = fmaf(hm, wreg[m].y, af);
            ag = fmaf(hm, wreg[m].z, ag);
            ao = fmaf(hm, wreg[m].w, ao);
        }
        float ig = sigf(ai);
        float fg = sigf(af);
        float gg = tnhf(ag);
        float og = sigf(ao);
        c = fmaf(fg, c, ig * gg);
        h = og * tnhf(c);
    }

    // ---- FC1: 19->16, tanh ----
    float a1 = sB1[u];
#pragma unroll
    for (int i = 0; i < 16; i++)
        a1 = fmaf(__shfl_sync(0xffffffffu, h, i, 16), sW1T[i * 16 + u], a1);
    a1 = fmaf(ctl0, sW1T[16 * 16 + u], a1);
    a1 = fmaf(ctl1, sW1T[17 * 16 + u], a1);
    a1 = fmaf(ctl2, sW1T[18 * 16 + u], a1);
    float x1 = tnhf(a1);

    // ---- FC2: 16->16, tanh ----
    float a2 = sB2[u];
#pragma unroll
    for (int i = 0; i < 16; i++)
        a2 = fmaf(__shfl_sync(0xffffffffu, x1, i, 16), sW2T[i * 16 + u], a2);
    float x2 = tnhf(a2);

    // ---- FC3: 16->1, relu; butterfly over 16-lane group ----
    float p = x2 * sW3[u];
#pragma unroll
    for (int off = 8; off; off >>= 1)
        p += __shfl_xor_sync(0xffffffffu, p, off, 16);

    if (u == 0) out[elem] = fmaxf(p + sB3[0], 0.0f);
}

extern "C" void kernel_launch(void* const* d_in, const int* in_sizes, int n_in,
                              void* d_out, int out_size)
{
    const float* mob  = (const float*)d_in[0];
    const float* ctrl = (const float*)d_in[1];
    const float* Wcc  = (const float*)d_in[3];
    const float* bcc  = (const float*)d_in[4];
    const float* Wih  = (const float*)d_in[5];
    const float* Whh  = (const float*)d_in[6];
    const float* bih  = (const float*)d_in[7];
    const float* bhh  = (const float*)d_in[8];
    const float* W1   = (const float*)d_in[9];
    const float* b1   = (const float*)d_in[10];
    const float* W2   = (const float*)d_in[11];
    const float* b2   = (const float*)d_in[12];
    const float* W3   = (const float*)d_in[13];
    const float* b3   = (const float*)d_in[14];

    int B = in_sizes[2];
    int blocks = (B + 15) / 16;     // 16 elements per 256-thread block

    infect_lstm_kernel<<<blocks, 256>>>(mob, ctrl, Wcc, bcc, Wih, Whh, bih, bhh,
                                        W1, b1, W2, b2, W3, b3, (float*)d_out);
}

// round 8
// speedup vs baseline: 9.2268x; 1.2381x over previous
#include <cuda_runtime.h>

// ---- hardware tanh (sm_75+; single MUFU op on sm_100) ----
__device__ __forceinline__ float tnha(float x) {
    float r; asm("tanh.approx.f32 %0, %1;" : "=f"(r) : "f"(x)); return r;
}
// sigmoid(x) = 0.5*tanh(x/2) + 0.5
__device__ __forceinline__ float siga(float x) {
    return fmaf(0.5f, tnha(0.5f * x), 0.5f);
}

// Block = 256 threads = 8 warps; each warp handles 2 elements (16 lanes each).
// Lane u owns hidden unit u. Whh weights live in registers for the hot loop.
__global__ void __launch_bounds__(256, 2) infect_lstm_kernel(
    const float* __restrict__ mob,   // [B,7]
    const float* __restrict__ ctrl,  // [B,5]
    const float* __restrict__ Wcc,   // [3,5]
    const float* __restrict__ bcc,   // [3]
    const float* __restrict__ Wih,   // [64,1]
    const float* __restrict__ Whh,   // [64,16]
    const float* __restrict__ bih,   // [64]
    const float* __restrict__ bhh,   // [64]
    const float* __restrict__ W1,    // [16,19]
    const float* __restrict__ b1,    // [16]
    const float* __restrict__ W2,    // [16,16]
    const float* __restrict__ b2,    // [16]
    const float* __restrict__ W3,    // [1,16]
    const float* __restrict__ b3,    // [1]
    float* __restrict__ out)         // [B]
{
    __shared__ __align__(16) float4 sWhhT[16 * 16]; // [m][u] -> (wi,wf,wg,wo)
    __shared__ __align__(16) float4 sWxB[16];       // [u] -> Wih per gate
    __shared__ __align__(16) float4 sBiasV[16];     // [u] -> bih+bhh per gate
    __shared__ float sW1T[19 * 16];                 // [i][u] = W1[u][i]
    __shared__ float sW2T[16 * 16];                 // [i][u] = W2[u][i]
    __shared__ float sW3[16], sB1[16], sB2[16];
    __shared__ float sWcc[15], sBcc[3], sB3[1];

    const int tid = threadIdx.x;

    {   // one entry per thread
        int m = tid >> 4, uu = tid & 15;
        sWhhT[tid] = make_float4(Whh[uu * 16 + m],
                                 Whh[(16 + uu) * 16 + m],
                                 Whh[(32 + uu) * 16 + m],
                                 Whh[(48 + uu) * 16 + m]);
        sW2T[tid] = W2[uu * 16 + m];   // [i=m][u]
    }
    for (int i = tid; i < 19 * 16; i += 256) {
        int col = i >> 4, uu = i & 15;
        sW1T[i] = W1[uu * 19 + col];
    }
    if (tid < 16) {
        int uu = tid;
        sWxB[uu]   = make_float4(Wih[uu], Wih[16 + uu], Wih[32 + uu], Wih[48 + uu]);
        sBiasV[uu] = make_float4(bih[uu]      + bhh[uu],
                                 bih[16 + uu] + bhh[16 + uu],
                                 bih[32 + uu] + bhh[32 + uu],
                                 bih[48 + uu] + bhh[48 + uu]);
        sW3[uu] = W3[uu]; sB1[uu] = b1[uu]; sB2[uu] = b2[uu];
    } else if (tid < 31) sWcc[tid - 16] = Wcc[tid - 16];
    else if (tid < 34) sBcc[tid - 31] = bcc[tid - 31];
    else if (tid == 34) sB3[0] = b3[0];
    __syncthreads();

    const int lane = tid & 31;
    const int u = lane & 15;
    const int gwarp = blockIdx.x * 8 + (tid >> 5);
    const int elem = gwarp * 2 + (lane >> 4);

    const float* mp = mob + (size_t)elem * 7;
    const float* cp = ctrl + (size_t)elem * 5;

    // ---- control head ----
    float ctl0 = sBcc[0], ctl1 = sBcc[1], ctl2 = sBcc[2];
#pragma unroll
    for (int i = 0; i < 5; i++) {
        float cv = cp[i];
        ctl0 = fmaf(cv, sWcc[i],      ctl0);
        ctl1 = fmaf(cv, sWcc[5 + i],  ctl1);
        ctl2 = fmaf(cv, sWcc[10 + i], ctl2);
    }

    // ---- hoist this lane's Whh column set into registers (64 regs) ----
    float4 wreg[16];
#pragma unroll
    for (int m = 0; m < 16; m++) wreg[m] = sWhhT[m * 16 + u];

    const float4 wx = sWxB[u];
    const float4 bb = sBiasV[u];
    float h = 0.0f, c = 0.0f;

    // ---- LSTM: 7 steps, fully unrolled; zero LDS inside ----
#pragma unroll
    for (int s = 0; s < 7; s++) {
        const float x = mp[s];
        float ai = fmaf(x, wx.x, bb.x);
        float af = fmaf(x, wx.y, bb.y);
        float ag = fmaf(x, wx.z, bb.z);
        float ao = fmaf(x, wx.w, bb.w);
#pragma unroll
        for (int m = 0; m < 16; m++) {
            float hm = __shfl_sync(0xffffffffu, h, m, 16);
            ai = fmaf(hm, wreg[m].x, ai);
            af = fmaf(hm, wreg[m].y, af);
            ag = fmaf(hm, wreg[m].z, ag);
            ao = fmaf(hm, wreg[m].w, ao);
        }
        float ig = siga(ai);
        float fg = siga(af);
        float gg = tnha(ag);
        float og = siga(ao);
        c = fmaf(fg, c, ig * gg);
        h = og * tnha(c);
    }

    // ---- FC1: 19->16, tanh ----
    float a1 = sB1[u];
#pragma unroll
    for (int i = 0; i < 16; i++)
        a1 = fmaf(__shfl_sync(0xffffffffu, h, i, 16), sW1T[i * 16 + u], a1);
    a1 = fmaf(ctl0, sW1T[16 * 16 + u], a1);
    a1 = fmaf(ctl1, sW1T[17 * 16 + u], a1);
    a1 = fmaf(ctl2, sW1T[18 * 16 + u], a1);
    float x1 = tnha(a1);

    // ---- FC2: 16->16, tanh ----
    float a2 = sB2[u];
#pragma unroll
    for (int i = 0; i < 16; i++)
        a2 = fmaf(__shfl_sync(0xffffffffu, x1, i, 16), sW2T[i * 16 + u], a2);
    float x2 = tnha(a2);

    // ---- FC3: 16->1, relu; butterfly over 16-lane group ----
    float p = x2 * sW3[u];
#pragma unroll
    for (int off = 8; off; off >>= 1)
        p += __shfl_xor_sync(0xffffffffu, p, off, 16);

    if (u == 0) out[elem] = fmaxf(p + sB3[0], 0.0f);
}

extern "C" void kernel_launch(void* const* d_in, const int* in_sizes, int n_in,
                              void* d_out, int out_size)
{
    const float* mob  = (const float*)d_in[0];
    const float* ctrl = (const float*)d_in[1];
    const float* Wcc  = (const float*)d_in[3];
    const float* bcc  = (const float*)d_in[4];
    const float* Wih  = (const float*)d_in[5];
    const float* Whh  = (const float*)d_in[6];
    const float* bih  = (const float*)d_in[7];
    const float* bhh  = (const float*)d_in[8];
    const float* W1   = (const float*)d_in[9];
    const float* b1   = (const float*)d_in[10];
    const float* W2   = (const float*)d_in[11];
    const float* b2   = (const float*)d_in[12];
    const float* W3   = (const float*)d_in[13];
    const float* b3   = (const float*)d_in[14];

    int B = in_sizes[2];
    int blocks = (B + 15) / 16;     // 16 elements per 256-thread block

    infect_lstm_kernel<<<blocks, 256>>>(mob, ctrl, Wcc, bcc, Wih, Whh, bih, bhh,
                                        W1, b1, W2, b2, W3, b3, (float*)d_out);
}

// round 9
// speedup vs baseline: 9.7846x; 1.0605x over previous
#include <cuda_runtime.h>

// ---- hardware tanh (single MUFU op on sm_100) ----
__device__ __forceinline__ float tnha(float x) {
    float r; asm("tanh.approx.f32 %0, %1;" : "=f"(r) : "f"(x)); return r;
}
// sigmoid(x) = 0.5*tanh(x/2) + 0.5
__device__ __forceinline__ float siga(float x) {
    return fmaf(0.5f, tnha(0.5f * x), 0.5f);
}

// Block = 256 threads = 8 warps; each warp handles 2 elements (16 lanes each).
// Lane u owns hidden unit u. Whh in registers; h exchanged via double-buffered smem.
__global__ void __launch_bounds__(256, 2) infect_lstm_kernel(
    const float* __restrict__ mob,   // [B,7]
    const float* __restrict__ ctrl,  // [B,5]
    const float* __restrict__ Wcc,   // [3,5]
    const float* __restrict__ bcc,   // [3]
    const float* __restrict__ Wih,   // [64,1]
    const float* __restrict__ Whh,   // [64,16]
    const float* __restrict__ bih,   // [64]
    const float* __restrict__ bhh,   // [64]
    const float* __restrict__ W1,    // [16,19]
    const float* __restrict__ b1,    // [16]
    const float* __restrict__ W2,    // [16,16]
    const float* __restrict__ b2,    // [16]
    const float* __restrict__ W3,    // [1,16]
    const float* __restrict__ b3,    // [1]
    float* __restrict__ out)         // [B]
{
    __shared__ __align__(16) float4 sWhhT[16 * 16]; // [m][u] -> (wi,wf,wg,wo)
    __shared__ __align__(16) float4 sWxB[16];       // [u] -> Wih per gate
    __shared__ __align__(16) float4 sBiasV[16];     // [u] -> bih+bhh per gate
    __shared__ float sW1T[19 * 16];                 // [i][u] = W1[u][i]
    __shared__ float sW2T[16 * 16];                 // [i][u] = W2[u][i]
    __shared__ float sW3[16], sB1[16], sB2[16];
    __shared__ float sWcc[15], sBcc[3], sB3[1];
    // h exchange: [slot][warp][group*16+u], double-buffered
    __shared__ __align__(16) float sH[2][8][32];

    const int tid = threadIdx.x;

    {   // one entry per thread
        int m = tid >> 4, uu = tid & 15;
        sWhhT[tid] = make_float4(Whh[uu * 16 + m],
                                 Whh[(16 + uu) * 16 + m],
                                 Whh[(32 + uu) * 16 + m],
                                 Whh[(48 + uu) * 16 + m]);
        sW2T[tid] = W2[uu * 16 + m];   // [i=m][u]
    }
    for (int i = tid; i < 19 * 16; i += 256) {
        int col = i >> 4, uu = i & 15;
        sW1T[i] = W1[uu * 19 + col];
    }
    if (tid < 16) {
        int uu = tid;
        sWxB[uu]   = make_float4(Wih[uu], Wih[16 + uu], Wih[32 + uu], Wih[48 + uu]);
        sBiasV[uu] = make_float4(bih[uu]      + bhh[uu],
                                 bih[16 + uu] + bhh[16 + uu],
                                 bih[32 + uu] + bhh[32 + uu],
                                 bih[48 + uu] + bhh[48 + uu]);
        sW3[uu] = W3[uu]; sB1[uu] = b1[uu]; sB2[uu] = b2[uu];
    } else if (tid < 31) sWcc[tid - 16] = Wcc[tid - 16];
    else if (tid < 34) sBcc[tid - 31] = bcc[tid - 31];
    else if (tid == 34) sB3[0] = b3[0];
    __syncthreads();

    const int lane = tid & 31;
    const int u = lane & 15;
    const int g = lane >> 4;                 // element group within warp (0/1)
    const int w = tid >> 5;                  // warp id within block
    const int gwarp = blockIdx.x * 8 + w;
    const int elem = gwarp * 2 + g;

    const float* mp = mob + (size_t)elem * 7;
    const float* cp = ctrl + (size_t)elem * 5;

    float* hb0 = &sH[0][w][g * 16];          // slot 0, this group's 16 floats
    float* hb1 = &sH[1][w][g * 16];          // slot 1

    // ---- control head ----
    float ctl0 = sBcc[0], ctl1 = sBcc[1], ctl2 = sBcc[2];
#pragma unroll
    for (int i = 0; i < 5; i++) {
        float cv = cp[i];
        ctl0 = fmaf(cv, sWcc[i],      ctl0);
        ctl1 = fmaf(cv, sWcc[5 + i],  ctl1);
        ctl2 = fmaf(cv, sWcc[10 + i], ctl2);
    }

    // ---- hoist this lane's Whh column set into registers (64 regs) ----
    float4 wreg[16];
#pragma unroll
    for (int m = 0; m < 16; m++) wreg[m] = sWhhT[m * 16 + u];

    const float4 wx = sWxB[u];
    const float4 bb = sBiasV[u];
    float c = 0.0f;

    hb0[u] = 0.0f;                           // h_0 = 0 in slot 0
    __syncwarp();

    // ---- LSTM: 7 steps; broadcast via double-buffered smem, 1 syncwarp/step ----
#pragma unroll
    for (int s = 0; s < 7; s++) {
        const float* hr = (s & 1) ? hb1 : hb0;   // read slot s&1
        float*       hw = (s & 1) ? hb0 : hb1;   // write slot (s+1)&1
        const float x = mp[s];
        float ai = fmaf(x, wx.x, bb.x);
        float af = fmaf(x, wx.y, bb.y);
        float ag = fmaf(x, wx.z, bb.z);
        float ao = fmaf(x, wx.w, bb.w);
#pragma unroll
        for (int m4 = 0; m4 < 4; m4++) {
            float4 hv = ((const float4*)hr)[m4];   // broadcast read
            const float4 w0 = wreg[m4 * 4 + 0];
            const float4 w1 = wreg[m4 * 4 + 1];
            const float4 w2 = wreg[m4 * 4 + 2];
            const float4 w3 = wreg[m4 * 4 + 3];
            ai = fmaf(hv.x, w0.x, ai); af = fmaf(hv.x, w0.y, af);
            ag = fmaf(hv.x, w0.z, ag); ao = fmaf(hv.x, w0.w, ao);
            ai = fmaf(hv.y, w1.x, ai); af = fmaf(hv.y, w1.y, af);
            ag = fmaf(hv.y, w1.z, ag); ao = fmaf(hv.y, w1.w, ao);
            ai = fmaf(hv.z, w2.x, ai); af = fmaf(hv.z, w2.y, af);
            ag = fmaf(hv.z, w2.z, ag); ao = fmaf(hv.z, w2.w, ao);
            ai = fmaf(hv.w, w3.x, ai); af = fmaf(hv.w, w3.y, af);
            ag = fmaf(hv.w, w3.z, ag); ao = fmaf(hv.w, w3.w, ao);
        }
        float ig = siga(ai);
        float fg = siga(af);
        float gg = tnha(ag);
        float og = siga(ao);
        c = fmaf(fg, c, ig * gg);
        hw[u] = og * tnha(c);
        __syncwarp();
    }
    // final h is in slot (7)&1 == 1

    // ---- FC1: 19->16, tanh (h read from smem, no shfl) ----
    float a1 = sB1[u];
#pragma unroll
    for (int m4 = 0; m4 < 4; m4++) {
        float4 hv = ((const float4*)hb1)[m4];
        a1 = fmaf(hv.x, sW1T[(m4 * 4 + 0) * 16 + u], a1);
        a1 = fmaf(hv.y, sW1T[(m4 * 4 + 1) * 16 + u], a1);
        a1 = fmaf(hv.z, sW1T[(m4 * 4 + 2) * 16 + u], a1);
        a1 = fmaf(hv.w, sW1T[(m4 * 4 + 3) * 16 + u], a1);
    }
    a1 = fmaf(ctl0, sW1T[16 * 16 + u], a1);
    a1 = fmaf(ctl1, sW1T[17 * 16 + u], a1);
    a1 = fmaf(ctl2, sW1T[18 * 16 + u], a1);
    float x1 = tnha(a1);

    // ---- FC2: 16->16, tanh (x1 exchanged via smem slot 0) ----
    hb0[u] = x1;
    __syncwarp();
    float a2 = sB2[u];
#pragma unroll
    for (int m4 = 0; m4 < 4; m4++) {
        float4 xv = ((const float4*)hb0)[m4];
        a2 = fmaf(xv.x, sW2T[(m4 * 4 + 0) * 16 + u], a2);
        a2 = fmaf(xv.y, sW2T[(m4 * 4 + 1) * 16 + u], a2);
        a2 = fmaf(xv.z, sW2T[(m4 * 4 + 2) * 16 + u], a2);
        a2 = fmaf(xv.w, sW2T[(m4 * 4 + 3) * 16 + u], a2);
    }
    float x2 = tnha(a2);

    // ---- FC3: 16->1, relu; butterfly over 16-lane group ----
    float p = x2 * sW3[u];
#pragma unroll
    for (int off = 8; off; off >>= 1)
        p += __shfl_xor_sync(0xffffffffu, p, off, 16);

    if (u == 0) out[elem] = fmaxf(p + sB3[0], 0.0f);
}

extern "C" void kernel_launch(void* const* d_in, const int* in_sizes, int n_in,
                              void* d_out, int out_size)
{
    const float* mob  = (const float*)d_in[0];
    const float* ctrl = (const float*)d_in[1];
    const float* Wcc  = (const float*)d_in[3];
    const float* bcc  = (const float*)d_in[4];
    const float* Wih  = (const float*)d_in[5];
    const float* Whh  = (const float*)d_in[6];
    const float* bih  = (const float*)d_in[7];
    const float* bhh  = (const float*)d_in[8];
    const float* W1   = (const float*)d_in[9];
    const float* b1   = (const float*)d_in[10];
    const float* W2   = (const float*)d_in[11];
    const float* b2   = (const float*)d_in[12];
    const float* W3   = (const float*)d_in[13];
    const float* b3   = (const float*)d_in[14];

    int B = in_sizes[2];
    int blocks = (B + 15) / 16;     // 16 elements per 256-thread block

    infect_lstm_kernel<<<blocks, 256>>>(mob, ctrl, Wcc, bcc, Wih, Whh, bih, bhh,
                                        W1, b1, W2, b2, W3, b3, (float*)d_out);
}

// round 10
// speedup vs baseline: 10.0714x; 1.0293x over previous
#include <cuda_runtime.h>

// ---- hardware tanh (single MUFU op on sm_100) ----
__device__ __forceinline__ float tnha(float x) {
    float r; asm("tanh.approx.f32 %0, %1;" : "=f"(r) : "f"(x)); return r;
}
// sigmoid(x) = 0.5*tanh(x/2) + 0.5
__device__ __forceinline__ float siga(float x) {
    return fmaf(0.5f, tnha(0.5f * x), 0.5f);
}

#define NW 4   // warps per block
// Block = 128 threads = 4 warps; each warp handles 2 elements (16 lanes each).
// Lane u owns hidden unit u. Whh in registers; h exchanged via double-buffered smem.
__global__ void __launch_bounds__(128, 5) infect_lstm_kernel(
    const float* __restrict__ mob,   // [B,7]
    const float* __restrict__ ctrl,  // [B,5]
    const float* __restrict__ Wcc,   // [3,5]
    const float* __restrict__ bcc,   // [3]
    const float* __restrict__ Wih,   // [64,1]
    const float* __restrict__ Whh,   // [64,16]
    const float* __restrict__ bih,   // [64]
    const float* __restrict__ bhh,   // [64]
    const float* __restrict__ W1,    // [16,19]
    const float* __restrict__ b1,    // [16]
    const float* __restrict__ W2,    // [16,16]
    const float* __restrict__ b2,    // [16]
    const float* __restrict__ W3,    // [1,16]
    const float* __restrict__ b3,    // [1]
    float* __restrict__ out)         // [B]
{
    __shared__ __align__(16) float4 sWhhT[16 * 16]; // [m][u] -> (wi,wf,wg,wo)
    __shared__ __align__(16) float4 sWxB[16];       // [u] -> Wih per gate
    __shared__ __align__(16) float4 sBiasV[16];     // [u] -> bih+bhh per gate
    __shared__ float sW1T[19 * 16];                 // [i][u] = W1[u][i]
    __shared__ float sW2T[16 * 16];                 // [i][u] = W2[u][i]
    __shared__ float sW3[16], sB1[16], sB2[16];
    __shared__ float sWcc[15], sBcc[3], sB3[1];
    __shared__ __align__(16) float sH[2][NW][32];   // h exchange, double-buffered

    const int tid = threadIdx.x;

    for (int i = tid; i < 256; i += 128) {
        int m = i >> 4, uu = i & 15;
        sWhhT[i] = make_float4(Whh[uu * 16 + m],
                               Whh[(16 + uu) * 16 + m],
                               Whh[(32 + uu) * 16 + m],
                               Whh[(48 + uu) * 16 + m]);
        sW2T[i] = W2[uu * 16 + m];   // [i=m][u]
    }
    for (int i = tid; i < 19 * 16; i += 128) {
        int col = i >> 4, uu = i & 15;
        sW1T[i] = W1[uu * 19 + col];
    }
    if (tid < 16) {
        int uu = tid;
        sWxB[uu]   = make_float4(Wih[uu], Wih[16 + uu], Wih[32 + uu], Wih[48 + uu]);
        sBiasV[uu] = make_float4(bih[uu]      + bhh[uu],
                                 bih[16 + uu] + bhh[16 + uu],
                                 bih[32 + uu] + bhh[32 + uu],
                                 bih[48 + uu] + bhh[48 + uu]);
        sW3[uu] = W3[uu]; sB1[uu] = b1[uu]; sB2[uu] = b2[uu];
    } else if (tid < 31) sWcc[tid - 16] = Wcc[tid - 16];
    else if (tid < 34) sBcc[tid - 31] = bcc[tid - 31];
    else if (tid == 34) sB3[0] = b3[0];
    __syncthreads();

    const int lane = tid & 31;
    const int u = lane & 15;
    const int g = lane >> 4;                 // element group within warp (0/1)
    const int w = tid >> 5;                  // warp id within block
    const int gwarp = blockIdx.x * NW + w;
    const int elem = gwarp * 2 + g;

    const float* mp = mob + (size_t)elem * 7;

    float* hb0 = &sH[0][w][g * 16];
    float* hb1 = &sH[1][w][g * 16];

    // ---- hoist this lane's Whh column set into registers (64 regs) ----
    float4 wreg[16];
#pragma unroll
    for (int m = 0; m < 16; m++) wreg[m] = sWhhT[m * 16 + u];

    const float4 wx = sWxB[u];
    const float4 bb = sBiasV[u];
    float c = 0.0f;

    hb0[u] = 0.0f;                           // h_0 = 0 in slot 0
    __syncwarp();

    // ---- LSTM: 7 steps, unrolled; split accumulators (chain depth 8) ----
#pragma unroll
    for (int s = 0; s < 7; s++) {
        const float* hr = (s & 1) ? hb1 : hb0;
        float*       hw = (s & 1) ? hb0 : hb1;
        const float x = mp[s];
        // partial set 0 carries bias+input term; set 1 starts at 0
        float ai0 = fmaf(x, wx.x, bb.x), ai1 = 0.0f;
        float af0 = fmaf(x, wx.y, bb.y), af1 = 0.0f;
        float ag0 = fmaf(x, wx.z, bb.z), ag1 = 0.0f;
        float ao0 = fmaf(x, wx.w, bb.w), ao1 = 0.0f;
#pragma unroll
        for (int m4 = 0; m4 < 2; m4++) {     // first half -> set 0
            float4 hv = ((const float4*)hr)[m4];
            const float4 w0 = wreg[m4 * 4 + 0];
            const float4 w1 = wreg[m4 * 4 + 1];
            const float4 w2 = wreg[m4 * 4 + 2];
            const float4 w3 = wreg[m4 * 4 + 3];
            ai0 = fmaf(hv.x, w0.x, ai0); af0 = fmaf(hv.x, w0.y, af0);
            ag0 = fmaf(hv.x, w0.z, ag0); ao0 = fmaf(hv.x, w0.w, ao0);
            ai0 = fmaf(hv.y, w1.x, ai0); af0 = fmaf(hv.y, w1.y, af0);
            ag0 = fmaf(hv.y, w1.z, ag0); ao0 = fmaf(hv.y, w1.w, ao0);
            ai0 = fmaf(hv.z, w2.x, ai0); af0 = fmaf(hv.z, w2.y, af0);
            ag0 = fmaf(hv.z, w2.z, ag0); ao0 = fmaf(hv.z, w2.w, ao0);
            ai0 = fmaf(hv.w, w3.x, ai0); af0 = fmaf(hv.w, w3.y, af0);
            ag0 = fmaf(hv.w, w3.z, ag0); ao0 = fmaf(hv.w, w3.w, ao0);
        }
#pragma unroll
        for (int m4 = 2; m4 < 4; m4++) {     // second half -> set 1
            float4 hv = ((const float4*)hr)[m4];
            const float4 w0 = wreg[m4 * 4 + 0];
            const float4 w1 = wreg[m4 * 4 + 1];
            const float4 w2 = wreg[m4 * 4 + 2];
            const float4 w3 = wreg[m4 * 4 + 3];
            ai1 = fmaf(hv.x, w0.x, ai1); af1 = fmaf(hv.x, w0.y, af1);
            ag1 = fmaf(hv.x, w0.z, ag1); ao1 = fmaf(hv.x, w0.w, ao1);
            ai1 = fmaf(hv.y, w1.x, ai1); af1 = fmaf(hv.y, w1.y, af1);
            ag1 = fmaf(hv.y, w1.z, ag1); ao1 = fmaf(hv.y, w1.w, ao1);
            ai1 = fmaf(hv.z, w2.x, ai1); af1 = fmaf(hv.z, w2.y, af1);
            ag1 = fmaf(hv.z, w2.z, ag1); ao1 = fmaf(hv.z, w2.w, ao1);
            ai1 = fmaf(hv.w, w3.x, ai1); af1 = fmaf(hv.w, w3.y, af1);
            ag1 = fmaf(hv.w, w3.z, ag1); ao1 = fmaf(hv.w, w3.w, ao1);
        }
        float ig = siga(ai0 + ai1);
        float fg = siga(af0 + af1);
        float gg = tnha(ag0 + ag1);
        float og = siga(ao0 + ao1);
        c = fmaf(fg, c, ig * gg);
        hw[u] = og * tnha(c);
        __syncwarp();
    }
    // final h is in slot 1

    // ---- control head (after LSTM to cut hot-loop register pressure) ----
    const float* cp = ctrl + (size_t)elem * 5;
    float ctl0 = sBcc[0], ctl1 = sBcc[1], ctl2 = sBcc[2];
#pragma unroll
    for (int i = 0; i < 5; i++) {
        float cv = cp[i];
        ctl0 = fmaf(cv, sWcc[i],      ctl0);
        ctl1 = fmaf(cv, sWcc[5 + i],  ctl1);
        ctl2 = fmaf(cv, sWcc[10 + i], ctl2);
    }

    // ---- FC1: 19->16, tanh ----
    float a1 = sB1[u];
#pragma unroll
    for (int m4 = 0; m4 < 4; m4++) {
        float4 hv = ((const float4*)hb1)[m4];
        a1 = fmaf(hv.x, sW1T[(m4 * 4 + 0) * 16 + u], a1);
        a1 = fmaf(hv.y, sW1T[(m4 * 4 + 1) * 16 + u], a1);
        a1 = fmaf(hv.z, sW1T[(m4 * 4 + 2) * 16 + u], a1);
        a1 = fmaf(hv.w, sW1T[(m4 * 4 + 3) * 16 + u], a1);
    }
    a1 = fmaf(ctl0, sW1T[16 * 16 + u], a1);
    a1 = fmaf(ctl1, sW1T[17 * 16 + u], a1);
    a1 = fmaf(ctl2, sW1T[18 * 16 + u], a1);
    float x1 = tnha(a1);

    // ---- FC2: 16->16, tanh ----
    hb0[u] = x1;
    __syncwarp();
    float a2 = sB2[u];
#pragma unroll
    for (int m4 = 0; m4 < 4; m4++) {
        float4 xv = ((const float4*)hb0)[m4];
        a2 = fmaf(xv.x, sW2T[(m4 * 4 + 0) * 16 + u], a2);
        a2 = fmaf(xv.y, sW2T[(m4 * 4 + 1) * 16 + u], a2);
        a2 = fmaf(xv.z, sW2T[(m4 * 4 + 2) * 16 + u], a2);
        a2 = fmaf(xv.w, sW2T[(m4 * 4 + 3) * 16 + u], a2);
    }
    float x2 = tnha(a2);

    // ---- FC3: 16->1, relu; butterfly over 16-lane group ----
    float p = x2 * sW3[u];
#pragma unroll
    for (int off = 8; off; off >>= 1)
        p += __shfl_xor_sync(0xffffffffu, p, off, 16);

    if (u == 0) out[elem] = fmaxf(p + sB3[0], 0.0f);
}

extern "C" void kernel_launch(void* const* d_in, const int* in_sizes, int n_in,
                              void* d_out, int out_size)
{
    const float* mob  = (const float*)d_in[0];
    const float* ctrl = (const float*)d_in[1];
    const float* Wcc  = (const float*)d_in[3];
    const float* bcc  = (const float*)d_in[4];
    const float* Wih  = (const float*)d_in[5];
    const float* Whh  = (const float*)d_in[6];
    const float* bih  = (const float*)d_in[7];
    const float* bhh  = (const float*)d_in[8];
    const float* W1   = (const float*)d_in[9];
    const float* b1   = (const float*)d_in[10];
    const float* W2   = (const float*)d_in[11];
    const float* b2   = (const float*)d_in[12];
    const float* W3   = (const float*)d_in[13];
    const float* b3   = (const float*)d_in[14];

    int B = in_sizes[2];
    int blocks = (B + 2 * NW - 1) / (2 * NW);   // 8 elements per 128-thread block

    infect_lstm_kernel<<<blocks, 128>>>(mob, ctrl, Wcc, bcc, Wih, Whh, bih, bhh,
                                        W1, b1, W2, b2, W3, b3, (float*)d_out);
}

// round 12
// speedup vs baseline: 12.6783x; 1.2588x over previous
#include <cuda_runtime.h>

// ---- hardware tanh (single MUFU op on sm_100) ----
__device__ __forceinline__ float tnha(float x) {
    float r; asm("tanh.approx.f32 %0, %1;" : "=f"(r) : "f"(x)); return r;
}
// sigmoid(x) = 0.5*tanh(x/2) + 0.5
__device__ __forceinline__ float siga(float x) {
    return fmaf(0.5f, tnha(0.5f * x), 0.5f);
}

#define NW 4   // warps per block
// Block = 128 threads = 4 warps; each warp handles 4 elements:
// lanes 0-15 = groups for elements {0,2}, lanes 16-31 = elements {1,3}.
// Each thread processes hidden unit u for TWO elements (A and B), sharing
// the register-resident Whh between them.
__global__ void __launch_bounds__(128, 4) infect_lstm_kernel(
    const float* __restrict__ mob,   // [B,7]
    const float* __restrict__ ctrl,  // [B,5]
    const float* __restrict__ Wcc,   // [3,5]
    const float* __restrict__ bcc,   // [3]
    const float* __restrict__ Wih,   // [64,1]
    const float* __restrict__ Whh,   // [64,16]
    const float* __restrict__ bih,   // [64]
    const float* __restrict__ bhh,   // [64]
    const float* __restrict__ W1,    // [16,19]
    const float* __restrict__ b1,    // [16]
    const float* __restrict__ W2,    // [16,16]
    const float* __restrict__ b2,    // [16]
    const float* __restrict__ W3,    // [1,16]
    const float* __restrict__ b3,    // [1]
    float* __restrict__ out)         // [B]
{
    __shared__ __align__(16) float4 sWhhT[16 * 16]; // [m][u] -> (wi,wf,wg,wo)
    __shared__ __align__(16) float4 sWxB[16];       // [u] -> Wih per gate
    __shared__ __align__(16) float4 sBiasV[16];     // [u] -> bih+bhh per gate
    __shared__ float sW1T[19 * 16];                 // [i][u] = W1[u][i]
    __shared__ float sW2T[16 * 16];                 // [i][u] = W2[u][i]
    __shared__ float sW3[16], sB1[16], sB2[16];
    __shared__ float sWcc[15], sBcc[3], sB3[1];
    // h exchange: [slot][warp][elemLocal*16+u], 4 elements per warp, double-buffered
    __shared__ __align__(16) float sH[2][NW][64];

    const int tid = threadIdx.x;

    for (int i = tid; i < 256; i += 128) {
        int m = i >> 4, uu = i & 15;
        sWhhT[i] = make_float4(Whh[uu * 16 + m],
                               Whh[(16 + uu) * 16 + m],
                               Whh[(32 + uu) * 16 + m],
                               Whh[(48 + uu) * 16 + m]);
        sW2T[i] = W2[uu * 16 + m];   // [i=m][u]
    }
    for (int i = tid; i < 19 * 16; i += 128) {
        int col = i >> 4, uu = i & 15;
        sW1T[i] = W1[uu * 19 + col];
    }
    if (tid < 16) {
        int uu = tid;
        sWxB[uu]   = make_float4(Wih[uu], Wih[16 + uu], Wih[32 + uu], Wih[48 + uu]);
        sBiasV[uu] = make_float4(bih[uu]      + bhh[uu],
                                 bih[16 + uu] + bhh[16 + uu],
                                 bih[32 + uu] + bhh[32 + uu],
                                 bih[48 + uu] + bhh[48 + uu]);
        sW3[uu] = W3[uu]; sB1[uu] = b1[uu]; sB2[uu] = b2[uu];
    } else if (tid < 31) sWcc[tid - 16] = Wcc[tid - 16];
    else if (tid < 34) sBcc[tid - 31] = bcc[tid - 31];
    else if (tid == 34) sB3[0] = b3[0];
    __syncthreads();

    const int lane = tid & 31;
    const int u = lane & 15;
    const int g = lane >> 4;                 // lane group (0/1)
    const int w = tid >> 5;                  // warp id within block
    const int gwarp = blockIdx.x * NW + w;
    const int eA = gwarp * 4 + g;            // element A (groups 0/1)
    const int eB = eA + 2;                   // element B (groups 2/3)

    const float* mpA = mob + (size_t)eA * 7;
    const float* mpB = mob + (size_t)eB * 7;

    // local-element h blocks: A at (g*16), B at ((2+g)*16)
    float* hA0 = &sH[0][w][g * 16];
    float* hA1 = &sH[1][w][g * 16];
    float* hB0 = &sH[0][w][(2 + g) * 16];
    float* hB1 = &sH[1][w][(2 + g) * 16];

    // ---- hoist this lane's Whh column set into registers (64 regs, shared A/B) ----
    float4 wreg[16];
#pragma unroll
    for (int m = 0; m < 16; m++) wreg[m] = sWhhT[m * 16 + u];

    const float4 wx = sWxB[u];
    const float4 bb = sBiasV[u];
    float cAc = 0.0f, cBc = 0.0f;

    hA0[u] = 0.0f;
    hB0[u] = 0.0f;
    __syncwarp();

    // ---- LSTM: 7 steps, unrolled; two independent elements per thread ----
#pragma unroll
    for (int s = 0; s < 7; s++) {
        const float* hAr = (s & 1) ? hA1 : hA0;
        float*       hAw = (s & 1) ? hA0 : hA1;
        const float* hBr = (s & 1) ? hB1 : hB0;
        float*       hBw = (s & 1) ? hB0 : hB1;
        const float xA = mpA[s];
        const float xB = mpB[s];
        float aiA = fmaf(xA, wx.x, bb.x), aiB = fmaf(xB, wx.x, bb.x);
        float afA = fmaf(xA, wx.y, bb.y), afB = fmaf(xB, wx.y, bb.y);
        float agA = fmaf(xA, wx.z, bb.z), agB = fmaf(xB, wx.z, bb.z);
        float aoA = fmaf(xA, wx.w, bb.w), aoB = fmaf(xB, wx.w, bb.w);
#pragma unroll
        for (int m4 = 0; m4 < 4; m4++) {
            float4 hvA = ((const float4*)hAr)[m4];
            float4 hvB = ((const float4*)hBr)[m4];
            const float4 w0 = wreg[m4 * 4 + 0];
            const float4 w1 = wreg[m4 * 4 + 1];
            const float4 w2 = wreg[m4 * 4 + 2];
            const float4 w3 = wreg[m4 * 4 + 3];
            aiA = fmaf(hvA.x, w0.x, aiA);  aiB = fmaf(hvB.x, w0.x, aiB);
            afA = fmaf(hvA.x, w0.y, afA);  afB = fmaf(hvB.x, w0.y, afB);
            agA = fmaf(hvA.x, w0.z, agA);  agB = fmaf(hvB.x, w0.z, agB);
            aoA = fmaf(hvA.x, w0.w, aoA);  aoB = fmaf(hvB.x, w0.w, aoB);
            aiA = fmaf(hvA.y, w1.x, aiA);  aiB = fmaf(hvB.y, w1.x, aiB);
            afA = fmaf(hvA.y, w1.y, afA);  afB = fmaf(hvB.y, w1.y, afB);
            agA = fmaf(hvA.y, w1.z, agA);  agB = fmaf(hvB.y, w1.z, agB);
            aoA = fmaf(hvA.y, w1.w, aoA);  aoB = fmaf(hvB.y, w1.w, aoB);
            aiA = fmaf(hvA.z, w2.x, aiA);  aiB = fmaf(hvB.z, w2.x, aiB);
            afA = fmaf(hvA.z, w2.y, afA);  afB = fmaf(hvB.z, w2.y, afB);
            agA = fmaf(hvA.z, w2.z, agA);  agB = fmaf(hvB.z, w2.z, agB);
            aoA = fmaf(hvA.z, w2.w, aoA);  aoB = fmaf(hvB.z, w2.w, aoB);
            aiA = fmaf(hvA.w, w3.x, aiA);  aiB = fmaf(hvB.w, w3.x, aiB);
            afA = fmaf(hvA.w, w3.y, afA);  afB = fmaf(hvB.w, w3.y, afB);
            agA = fmaf(hvA.w, w3.z, agA);  agB = fmaf(hvB.w, w3.z, agB);
            aoA = fmaf(hvA.w, w3.w, aoA);  aoB = fmaf(hvB.w, w3.w, aoB);
        }
        float igA = siga(aiA), igB = siga(aiB);
        float fgA = siga(afA), fgB = siga(afB);
        float ggA = tnha(agA), ggB = tnha(agB);
        float ogA = siga(aoA), ogB = siga(aoB);
        cAc = fmaf(fgA, cAc, igA * ggA);
        cBc = fmaf(fgB, cBc, igB * ggB);
        hAw[u] = ogA * tnha(cAc);
        hBw[u] = ogB * tnha(cBc);
        __syncwarp();
    }
    // final h is in slot 1

    // ---- control heads (post-loop to keep hot-loop pressure down) ----
    const float* cpA = ctrl + (size_t)eA * 5;
    const float* cpB = ctrl + (size_t)eB * 5;
    float c0A = sBcc[0], c1A = sBcc[1], c2A = sBcc[2];
    float c0B = sBcc[0], c1B = sBcc[1], c2B = sBcc[2];
#pragma unroll
    for (int i = 0; i < 5; i++) {
        float vA = cpA[i], vB = cpB[i];
        c0A = fmaf(vA, sWcc[i],      c0A);  c0B = fmaf(vB, sWcc[i],      c0B);
        c1A = fmaf(vA, sWcc[5 + i],  c1A);  c1B = fmaf(vB, sWcc[5 + i],  c1B);
        c2A = fmaf(vA, sWcc[10 + i], c2A);  c2B = fmaf(vB, sWcc[10 + i], c2B);
    }

    // ---- FC1: 19->16, tanh ----
    float a1A = sB1[u], a1B = a1A;
#pragma unroll
    for (int m4 = 0; m4 < 4; m4++) {
        float4 hvA = ((const float4*)hA1)[m4];
        float4 hvB = ((const float4*)hB1)[m4];
        float w0 = sW1T[(m4 * 4 + 0) * 16 + u];
        float w1 = sW1T[(m4 * 4 + 1) * 16 + u];
        float w2 = sW1T[(m4 * 4 + 2) * 16 + u];
        float w3 = sW1T[(m4 * 4 + 3) * 16 + u];
        a1A = fmaf(hvA.x, w0, a1A);  a1B = fmaf(hvB.x, w0, a1B);
        a1A = fmaf(hvA.y, w1, a1A);  a1B = fmaf(hvB.y, w1, a1B);
        a1A = fmaf(hvA.z, w2, a1A);  a1B = fmaf(hvB.z, w2, a1B);
        a1A = fmaf(hvA.w, w3, a1A);  a1B = fmaf(hvB.w, w3, a1B);
    }
    {
        float wc0 = sW1T[16 * 16 + u], wc1 = sW1T[17 * 16 + u], wc2 = sW1T[18 * 16 + u];
        a1A = fmaf(c0A, wc0, a1A);  a1B = fmaf(c0B, wc0, a1B);
        a1A = fmaf(c1A, wc1, a1A);  a1B = fmaf(c1B, wc1, a1B);
        a1A = fmaf(c2A, wc2, a1A);  a1B = fmaf(c2B, wc2, a1B);
    }
    float x1A = tnha(a1A), x1B = tnha(a1B);

    // ---- FC2: 16->16, tanh (exchange x1 via slot 0) ----
    hA0[u] = x1A;
    hB0[u] = x1B;
    __syncwarp();
    float a2A = sB2[u], a2B = a2A;
#pragma unroll
    for (int m4 = 0; m4 < 4; m4++) {
        float4 xvA = ((const float4*)hA0)[m4];
        float4 xvB = ((const float4*)hB0)[m4];
        float w0 = sW2T[(m4 * 4 + 0) * 16 + u];
        float w1 = sW2T[(m4 * 4 + 1) * 16 + u];
        float w2 = sW2T[(m4 * 4 + 2) * 16 + u];
        float w3 = sW2T[(m4 * 4 + 3) * 16 + u];
        a2A = fmaf(xvA.x, w0, a2A);  a2B = fmaf(xvB.x, w0, a2B);
        a2A = fmaf(xvA.y, w1, a2A);  a2B = fmaf(xvB.y, w1, a2B);
        a2A = fmaf(xvA.z, w2, a2A);  a2B = fmaf(xvB.z, w2, a2B);
        a2A = fmaf(xvA.w, w3, a2A);  a2B = fmaf(xvB.w, w3, a2B);
    }
    float x2A = tnha(a2A), x2B = tnha(a2B);

    // ---- FC3: 16->1, relu; butterfly over 16-lane group, both elements ----
    float pA = x2A * sW3[u];
    float pB = x2B * sW3[u];
#pragma unroll
    for (int off = 8; off; off >>= 1) {
        pA += __shfl_xor_sync(0xffffffffu, pA, off, 16);
        pB += __shfl_xor_sync(0xffffffffu, pB, off, 16);
    }

    if (u == 0) {
        out[eA] = fmaxf(pA + sB3[0], 0.0f);
        out[eB] = fmaxf(pB + sB3[0], 0.0f);
    }
}

extern "C" void kernel_launch(void* const* d_in, const int* in_sizes, int n_in,
                              void* d_out, int out_size)
{
    const float* mob  = (const float*)d_in[0];
    const float* ctrl = (const float*)d_in[1];
    const float* Wcc  = (const float*)d_in[3];
    const float* bcc  = (const float*)d_in[4];
    const float* Wih  = (const float*)d_in[5];
    const float* Whh  = (const float*)d_in[6];
    const float* bih  = (const float*)d_in[7];
    const float* bhh  = (const float*)d_in[8];
    const float* W1   = (const float*)d_in[9];
    const float* b1   = (const float*)d_in[10];
    const float* W2   = (const float*)d_in[11];
    const float* b2   = (const float*)d_in[12];
    const float* W3   = (const float*)d_in[13];
    const float* b3   = (const float*)d_in[14];

    int B = in_sizes[2];
    int blocks = (B + 4 * NW - 1) / (4 * NW);   // 16 elements per 128-thread block

    infect_lstm_kernel<<<blocks, 128>>>(mob, ctrl, Wcc, bcc, Wih, Whh, bih, bhh,
                                        W1, b1, W2, b2, W3, b3, (float*)d_out);
}

// round 13
// speedup vs baseline: 13.5364x; 1.0677x over previous
#include <cuda_runtime.h>

// ---- hardware tanh (single MUFU op on sm_100) ----
__device__ __forceinline__ float tnha(float x) {
    float r; asm("tanh.approx.f32 %0, %1;" : "=f"(r) : "f"(x)); return r;
}
// sigmoid(x) = 0.5*tanh(x/2) + 0.5
__device__ __forceinline__ float siga(float x) {
    return fmaf(0.5f, tnha(0.5f * x), 0.5f);
}

#define NW 4   // warps per block
#define EPT 4  // elements per thread
// Block = 128 threads = 4 warps; each warp handles 8 elements:
// lane groups (0/1) x 4 per-thread elements. Each thread processes hidden
// unit u for FOUR elements, sharing the register-resident Whh among them.
__global__ void __launch_bounds__(128, 3) infect_lstm_kernel(
    const float* __restrict__ mob,   // [B,7]
    const float* __restrict__ ctrl,  // [B,5]
    const float* __restrict__ Wcc,   // [3,5]
    const float* __restrict__ bcc,   // [3]
    const float* __restrict__ Wih,   // [64,1]
    const float* __restrict__ Whh,   // [64,16]
    const float* __restrict__ bih,   // [64]
    const float* __restrict__ bhh,   // [64]
    const float* __restrict__ W1,    // [16,19]
    const float* __restrict__ b1,    // [16]
    const float* __restrict__ W2,    // [16,16]
    const float* __restrict__ b2,    // [16]
    const float* __restrict__ W3,    // [1,16]
    const float* __restrict__ b3,    // [1]
    float* __restrict__ out)         // [B]
{
    __shared__ __align__(16) float4 sWhhT[16 * 16]; // [m][u] -> (wi,wf,wg,wo)
    __shared__ __align__(16) float4 sWxB[16];       // [u] -> Wih per gate
    __shared__ __align__(16) float4 sBiasV[16];     // [u] -> bih+bhh per gate
    __shared__ float sW1T[19 * 16];                 // [i][u] = W1[u][i]
    __shared__ float sW2T[16 * 16];                 // [i][u] = W2[u][i]
    __shared__ float sW3[16], sB1[16], sB2[16];
    __shared__ float sWcc[15], sBcc[3], sB3[1];
    // h exchange: [slot][warp][elemLocal*16+u], 8 elements per warp, double-buffered
    __shared__ __align__(16) float sH[2][NW][128];

    const int tid = threadIdx.x;

    for (int i = tid; i < 256; i += 128) {
        int m = i >> 4, uu = i & 15;
        sWhhT[i] = make_float4(Whh[uu * 16 + m],
                               Whh[(16 + uu) * 16 + m],
                               Whh[(32 + uu) * 16 + m],
                               Whh[(48 + uu) * 16 + m]);
        sW2T[i] = W2[uu * 16 + m];   // [i=m][u]
    }
    for (int i = tid; i < 19 * 16; i += 128) {
        int col = i >> 4, uu = i & 15;
        sW1T[i] = W1[uu * 19 + col];
    }
    if (tid < 16) {
        int uu = tid;
        sWxB[uu]   = make_float4(Wih[uu], Wih[16 + uu], Wih[32 + uu], Wih[48 + uu]);
        sBiasV[uu] = make_float4(bih[uu]      + bhh[uu],
                                 bih[16 + uu] + bhh[16 + uu],
                                 bih[32 + uu] + bhh[32 + uu],
                                 bih[48 + uu] + bhh[48 + uu]);
        sW3[uu] = W3[uu]; sB1[uu] = b1[uu]; sB2[uu] = b2[uu];
    } else if (tid < 31) sWcc[tid - 16] = Wcc[tid - 16];
    else if (tid < 34) sBcc[tid - 31] = bcc[tid - 31];
    else if (tid == 34) sB3[0] = b3[0];
    __syncthreads();

    const int lane = tid & 31;
    const int u = lane & 15;
    const int g = lane >> 4;                 // lane group (0/1)
    const int w = tid >> 5;                  // warp id within block
    const int gwarp = blockIdx.x * NW + w;
    const int ebase = gwarp * (2 * EPT);     // 8 elements per warp
    // element k of this thread: ebase + 2*k + g ; local h block index 2*k+g

    const float* mp[EPT];
#pragma unroll
    for (int k = 0; k < EPT; k++) mp[k] = mob + (size_t)(ebase + 2 * k + g) * 7;

    // ---- hoist this lane's Whh column set into registers (64 regs, shared) ----
    float4 wreg[16];
#pragma unroll
    for (int m = 0; m < 16; m++) wreg[m] = sWhhT[m * 16 + u];

    const float4 wx = sWxB[u];
    const float4 bb = sBiasV[u];
    float cc[EPT];
#pragma unroll
    for (int k = 0; k < EPT; k++) cc[k] = 0.0f;

#pragma unroll
    for (int k = 0; k < EPT; k++) sH[0][w][(2 * k + g) * 16 + u] = 0.0f;
    __syncwarp();

    // ---- LSTM: 7 steps, unrolled; four independent elements per thread ----
#pragma unroll
    for (int s = 0; s < 7; s++) {
        const int rp = s & 1, wp = rp ^ 1;
        float ai[EPT], af[EPT], ag[EPT], ao[EPT];
#pragma unroll
        for (int k = 0; k < EPT; k++) {
            float x = mp[k][s];
            ai[k] = fmaf(x, wx.x, bb.x);
            af[k] = fmaf(x, wx.y, bb.y);
            ag[k] = fmaf(x, wx.z, bb.z);
            ao[k] = fmaf(x, wx.w, bb.w);
        }
#pragma unroll
        for (int m4 = 0; m4 < 4; m4++) {
            const float4 w0 = wreg[m4 * 4 + 0];
            const float4 w1 = wreg[m4 * 4 + 1];
            const float4 w2 = wreg[m4 * 4 + 2];
            const float4 w3 = wreg[m4 * 4 + 3];
#pragma unroll
            for (int k = 0; k < EPT; k++) {
                float4 hv = *(const float4*)&sH[rp][w][(2 * k + g) * 16 + m4 * 4];
                ai[k] = fmaf(hv.x, w0.x, ai[k]);
                af[k] = fmaf(hv.x, w0.y, af[k]);
                ag[k] = fmaf(hv.x, w0.z, ag[k]);
                ao[k] = fmaf(hv.x, w0.w, ao[k]);
                ai[k] = fmaf(hv.y, w1.x, ai[k]);
                af[k] = fmaf(hv.y, w1.y, af[k]);
                ag[k] = fmaf(hv.y, w1.z, ag[k]);
                ao[k] = fmaf(hv.y, w1.w, ao[k]);
                ai[k] = fmaf(hv.z, w2.x, ai[k]);
                af[k] = fmaf(hv.z, w2.y, af[k]);
                ag[k] = fmaf(hv.z, w2.z, ag[k]);
                ao[k] = fmaf(hv.z, w2.w, ao[k]);
                ai[k] = fmaf(hv.w, w3.x, ai[k]);
                af[k] = fmaf(hv.w, w3.y, af[k]);
                ag[k] = fmaf(hv.w, w3.z, ag[k]);
                ao[k] = fmaf(hv.w, w3.w, ao[k]);
            }
        }
#pragma unroll
        for (int k = 0; k < EPT; k++) {
            float ig = siga(ai[k]);
            float fg = siga(af[k]);
            float gg = tnha(ag[k]);
            float og = siga(ao[k]);
            cc[k] = fmaf(fg, cc[k], ig * gg);
            sH[wp][w][(2 * k + g) * 16 + u] = og * tnha(cc[k]);
        }
        __syncwarp();
    }
    // final h is in slot 1

    // ---- control heads (post-loop) ----
    float c0[EPT], c1[EPT], c2[EPT];
#pragma unroll
    for (int k = 0; k < EPT; k++) { c0[k] = sBcc[0]; c1[k] = sBcc[1]; c2[k] = sBcc[2]; }
#pragma unroll
    for (int i = 0; i < 5; i++) {
        float wa = sWcc[i], wb = sWcc[5 + i], wc = sWcc[10 + i];
#pragma unroll
        for (int k = 0; k < EPT; k++) {
            float v = ctrl[(size_t)(ebase + 2 * k + g) * 5 + i];
            c0[k] = fmaf(v, wa, c0[k]);
            c1[k] = fmaf(v, wb, c1[k]);
            c2[k] = fmaf(v, wc, c2[k]);
        }
    }

    // ---- FC1: 19->16, tanh ----
    float a1[EPT];
#pragma unroll
    for (int k = 0; k < EPT; k++) a1[k] = sB1[u];
#pragma unroll
    for (int m4 = 0; m4 < 4; m4++) {
        float w0 = sW1T[(m4 * 4 + 0) * 16 + u];
        float w1 = sW1T[(m4 * 4 + 1) * 16 + u];
        float w2 = sW1T[(m4 * 4 + 2) * 16 + u];
        float w3 = sW1T[(m4 * 4 + 3) * 16 + u];
#pragma unroll
        for (int k = 0; k < EPT; k++) {
            float4 hv = *(const float4*)&sH[1][w][(2 * k + g) * 16 + m4 * 4];
            a1[k] = fmaf(hv.x, w0, a1[k]);
            a1[k] = fmaf(hv.y, w1, a1[k]);
            a1[k] = fmaf(hv.z, w2, a1[k]);
            a1[k] = fmaf(hv.w, w3, a1[k]);
        }
    }
    {
        float wc0 = sW1T[16 * 16 + u], wc1 = sW1T[17 * 16 + u], wc2 = sW1T[18 * 16 + u];
#pragma unroll
        for (int k = 0; k < EPT; k++) {
            a1[k] = fmaf(c0[k], wc0, a1[k]);
            a1[k] = fmaf(c1[k], wc1, a1[k]);
            a1[k] = fmaf(c2[k], wc2, a1[k]);
        }
    }
#pragma unroll
    for (int k = 0; k < EPT; k++) sH[0][w][(2 * k + g) * 16 + u] = tnha(a1[k]);
    __syncwarp();

    // ---- FC2: 16->16, tanh ----
    float a2[EPT];
#pragma unroll
    for (int k = 0; k < EPT; k++) a2[k] = sB2[u];
#pragma unroll
    for (int m4 = 0; m4 < 4; m4++) {
        float w0 = sW2T[(m4 * 4 + 0) * 16 + u];
        float w1 = sW2T[(m4 * 4 + 1) * 16 + u];
        float w2 = sW2T[(m4 * 4 + 2) * 16 + u];
        float w3 = sW2T[(m4 * 4 + 3) * 16 + u];
#pragma unroll
        for (int k = 0; k < EPT; k++) {
            float4 xv = *(const float4*)&sH[0][w][(2 * k + g) * 16 + m4 * 4];
            a2[k] = fmaf(xv.x, w0, a2[k]);
            a2[k] = fmaf(xv.y, w1, a2[k]);
            a2[k] = fmaf(xv.z, w2, a2[k]);
            a2[k] = fmaf(xv.w, w3, a2[k]);
        }
    }

    // ---- FC3: 16->1, relu; butterfly over 16-lane group, per element ----
    float w3v = sW3[u];
#pragma unroll
    for (int k = 0; k < EPT; k++) {
        float p = tnha(a2[k]) * w3v;
#pragma unroll
        for (int off = 8; off; off >>= 1)
            p += __shfl_xor_sync(0xffffffffu, p, off, 16);
        if (u == 0) out[ebase + 2 * k + g] = fmaxf(p + sB3[0], 0.0f);
    }
}

extern "C" void kernel_launch(void* const* d_in, const int* in_sizes, int n_in,
                              void* d_out, int out_size)
{
    const float* mob  = (const float*)d_in[0];
    const float* ctrl = (const float*)d_in[1];
    const float* Wcc  = (const float*)d_in[3];
    const float* bcc  = (const float*)d_in[4];
    const float* Wih  = (const float*)d_in[5];
    const float* Whh  = (const float*)d_in[6];
    const float* bih  = (const float*)d_in[7];
    const float* bhh  = (const float*)d_in[8];
    const float* W1   = (const float*)d_in[9];
    const float* b1   = (const float*)d_in[10];
    const float* W2   = (const float*)d_in[11];
    const float* b2   = (const float*)d_in[12];
    const float* W3   = (const float*)d_in[13];
    const float* b3   = (const float*)d_in[14];

    int B = in_sizes[2];
    int blocks = (B + 2 * EPT * NW - 1) / (2 * EPT * NW);  // 32 elements per block

    infect_lstm_kernel<<<blocks, 128>>>(mob, ctrl, Wcc, bcc, Wih, Whh, bih, bhh,
                                        W1, b1, W2, b2, W3, b3, (float*)d_out);
}

// round 14
// speedup vs baseline: 14.4942x; 1.0708x over previous
#include <cuda_runtime.h>

// ---- hardware tanh (single MUFU op on sm_100) ----
__device__ __forceinline__ float tnha(float x) {
    float r; asm("tanh.approx.f32 %0, %1;" : "=f"(r) : "f"(x)); return r;
}
// sigmoid(x) = 0.5*tanh(x/2) + 0.5
__device__ __forceinline__ float siga(float x) {
    return fmaf(0.5f, tnha(0.5f * x), 0.5f);
}

#define NW 4   // warps per block
#define EPT 4  // elements per thread
// Block = 128 threads = 4 warps; each warp handles 8 elements.
// Each thread processes hidden unit u for FOUR elements, sharing the
// register-resident Whh among them. Register-dieted to fit 4 blocks/SM.
__global__ void __launch_bounds__(128, 4) infect_lstm_kernel(
    const float* __restrict__ mob,   // [B,7]
    const float* __restrict__ ctrl,  // [B,5]
    const float* __restrict__ Wcc,   // [3,5]
    const float* __restrict__ bcc,   // [3]
    const float* __restrict__ Wih,   // [64,1]
    const float* __restrict__ Whh,   // [64,16]
    const float* __restrict__ bih,   // [64]
    const float* __restrict__ bhh,   // [64]
    const float* __restrict__ W1,    // [16,19]
    const float* __restrict__ b1,    // [16]
    const float* __restrict__ W2,    // [16,16]
    const float* __restrict__ b2,    // [16]
    const float* __restrict__ W3,    // [1,16]
    const float* __restrict__ b3,    // [1]
    float* __restrict__ out)         // [B]
{
    __shared__ __align__(16) float4 sWhhT[16 * 16]; // [m][u] -> (wi,wf,wg,wo)
    __shared__ __align__(16) float4 sWxB[16];       // [u] -> Wih per gate
    __shared__ __align__(16) float4 sBiasV[16];     // [u] -> bih+bhh per gate
    __shared__ float sW1T[19 * 16];                 // [i][u] = W1[u][i]
    __shared__ float sW2T[16 * 16];                 // [i][u] = W2[u][i]
    __shared__ float sW3[16], sB1[16], sB2[16];
    __shared__ float sWcc[15], sBcc[3], sB3[1];
    // h exchange: [slot][warp][elemLocal*16+u], 8 elements per warp, double-buffered
    __shared__ __align__(16) float sH[2][NW][128];

    const int tid = threadIdx.x;

    for (int i = tid; i < 256; i += 128) {
        int m = i >> 4, uu = i & 15;
        sWhhT[i] = make_float4(Whh[uu * 16 + m],
                               Whh[(16 + uu) * 16 + m],
                               Whh[(32 + uu) * 16 + m],
                               Whh[(48 + uu) * 16 + m]);
        sW2T[i] = W2[uu * 16 + m];   // [i=m][u]
    }
    for (int i = tid; i < 19 * 16; i += 128) {
        int col = i >> 4, uu = i & 15;
        sW1T[i] = W1[uu * 19 + col];
    }
    if (tid < 16) {
        int uu = tid;
        sWxB[uu]   = make_float4(Wih[uu], Wih[16 + uu], Wih[32 + uu], Wih[48 + uu]);
        sBiasV[uu] = make_float4(bih[uu]      + bhh[uu],
                                 bih[16 + uu] + bhh[16 + uu],
                                 bih[32 + uu] + bhh[32 + uu],
                                 bih[48 + uu] + bhh[48 + uu]);
        sW3[uu] = W3[uu]; sB1[uu] = b1[uu]; sB2[uu] = b2[uu];
    } else if (tid < 31) sWcc[tid - 16] = Wcc[tid - 16];
    else if (tid < 34) sBcc[tid - 31] = bcc[tid - 31];
    else if (tid == 34) sB3[0] = b3[0];
    __syncthreads();

    const int lane = tid & 31;
    const int u = lane & 15;
    const int g = lane >> 4;                 // lane group (0/1)
    const int w = tid >> 5;                  // warp id within block
    const int ebase = (blockIdx.x * NW + w) * (2 * EPT);  // 8 elements per warp
    // element k of this thread: ebase + 2*k + g ; local h block index 2*k+g

    // single base pointers; per-k offsets are compile-time immediates
    const float* mpg = mob  + (size_t)(ebase + g) * 7;   // element k at +14*k
    const float* cpg = ctrl + (size_t)(ebase + g) * 5;   // element k at +10*k

    // ---- hoist this lane's Whh column set into registers (64 regs, shared) ----
    float4 wreg[16];
#pragma unroll
    for (int m = 0; m < 16; m++) wreg[m] = sWhhT[m * 16 + u];

    const float4 wx = sWxB[u];
    const float4 bb = sBiasV[u];
    float cc[EPT];
#pragma unroll
    for (int k = 0; k < EPT; k++) cc[k] = 0.0f;

#pragma unroll
    for (int k = 0; k < EPT; k++) sH[0][w][(2 * k + g) * 16 + u] = 0.0f;
    __syncwarp();

    // ---- LSTM: 7 steps, unrolled; four independent elements per thread ----
#pragma unroll
    for (int s = 0; s < 7; s++) {
        const int rp = s & 1, wp = rp ^ 1;
        float ai[EPT], af[EPT], ag[EPT], ao[EPT];
#pragma unroll
        for (int k = 0; k < EPT; k++) {
            float x = mpg[14 * k + s];
            ai[k] = fmaf(x, wx.x, bb.x);
            af[k] = fmaf(x, wx.y, bb.y);
            ag[k] = fmaf(x, wx.z, bb.z);
            ao[k] = fmaf(x, wx.w, bb.w);
        }
#pragma unroll
        for (int m4 = 0; m4 < 4; m4++) {
            const float4 w0 = wreg[m4 * 4 + 0];
            const float4 w1 = wreg[m4 * 4 + 1];
            const float4 w2 = wreg[m4 * 4 + 2];
            const float4 w3 = wreg[m4 * 4 + 3];
#pragma unroll
            for (int k = 0; k < EPT; k++) {
                float4 hv = *(const float4*)&sH[rp][w][(2 * k + g) * 16 + m4 * 4];
                ai[k] = fmaf(hv.x, w0.x, ai[k]);
                af[k] = fmaf(hv.x, w0.y, af[k]);
                ag[k] = fmaf(hv.x, w0.z, ag[k]);
                ao[k] = fmaf(hv.x, w0.w, ao[k]);
                ai[k] = fmaf(hv.y, w1.x, ai[k]);
                af[k] = fmaf(hv.y, w1.y, af[k]);
                ag[k] = fmaf(hv.y, w1.z, ag[k]);
                ao[k] = fmaf(hv.y, w1.w, ao[k]);
                ai[k] = fmaf(hv.z, w2.x, ai[k]);
                af[k] = fmaf(hv.z, w2.y, af[k]);
                ag[k] = fmaf(hv.z, w2.z, ag[k]);
                ao[k] = fmaf(hv.z, w2.w, ao[k]);
                ai[k] = fmaf(hv.w, w3.x, ai[k]);
                af[k] = fmaf(hv.w, w3.y, af[k]);
                ag[k] = fmaf(hv.w, w3.z, ag[k]);
                ao[k] = fmaf(hv.w, w3.w, ao[k]);
            }
        }
#pragma unroll
        for (int k = 0; k < EPT; k++) {
            float ig = siga(ai[k]);
            float fg = siga(af[k]);
            float gg = tnha(ag[k]);
            float og = siga(ao[k]);
            cc[k] = fmaf(fg, cc[k], ig * gg);
            sH[wp][w][(2 * k + g) * 16 + u] = og * tnha(cc[k]);
        }
        __syncwarp();
    }
    // final h is in slot 1

    // ---- control heads (post-loop) ----
    float c0[EPT], c1[EPT], c2[EPT];
#pragma unroll
    for (int k = 0; k < EPT; k++) { c0[k] = sBcc[0]; c1[k] = sBcc[1]; c2[k] = sBcc[2]; }
#pragma unroll
    for (int i = 0; i < 5; i++) {
        float wa = sWcc[i], wb = sWcc[5 + i], wc = sWcc[10 + i];
#pragma unroll
        for (int k = 0; k < EPT; k++) {
            float v = cpg[10 * k + i];
            c0[k] = fmaf(v, wa, c0[k]);
            c1[k] = fmaf(v, wb, c1[k]);
            c2[k] = fmaf(v, wc, c2[k]);
        }
    }

    // ---- FC1: 19->16, tanh ----
    float a1[EPT];
#pragma unroll
    for (int k = 0; k < EPT; k++) a1[k] = sB1[u];
#pragma unroll
    for (int m4 = 0; m4 < 4; m4++) {
        float w0 = sW1T[(m4 * 4 + 0) * 16 + u];
        float w1 = sW1T[(m4 * 4 + 1) * 16 + u];
        float w2 = sW1T[(m4 * 4 + 2) * 16 + u];
        float w3 = sW1T[(m4 * 4 + 3) * 16 + u];
#pragma unroll
        for (int k = 0; k < EPT; k++) {
            float4 hv = *(const float4*)&sH[1][w][(2 * k + g) * 16 + m4 * 4];
            a1[k] = fmaf(hv.x, w0, a1[k]);
            a1[k] = fmaf(hv.y, w1, a1[k]);
            a1[k] = fmaf(hv.z, w2, a1[k]);
            a1[k] = fmaf(hv.w, w3, a1[k]);
        }
    }
    {
        float wc0 = sW1T[16 * 16 + u], wc1 = sW1T[17 * 16 + u], wc2 = sW1T[18 * 16 + u];
#pragma unroll
        for (int k = 0; k < EPT; k++) {
            a1[k] = fmaf(c0[k], wc0, a1[k]);
            a1[k] = fmaf(c1[k], wc1, a1[k]);
            a1[k] = fmaf(c2[k], wc2, a1[k]);
        }
    }
#pragma unroll
    for (int k = 0; k < EPT; k++) sH[0][w][(2 * k + g) * 16 + u] = tnha(a1[k]);
    __syncwarp();

    // ---- FC2: 16->16, tanh ----
    float a2[EPT];
#pragma unroll
    for (int k = 0; k < EPT; k++) a2[k] = sB2[u];
#pragma unroll
    for (int m4 = 0; m4 < 4; m4++) {
        float w0 = sW2T[(m4 * 4 + 0) * 16 + u];
        float w1 = sW2T[(m4 * 4 + 1) * 16 + u];
        float w2 = sW2T[(m4 * 4 + 2) * 16 + u];
        float w3 = sW2T[(m4 * 4 + 3) * 16 + u];
#pragma unroll
        for (int k = 0; k < EPT; k++) {
            float4 xv = *(const float4*)&sH[0][w][(2 * k + g) * 16 + m4 * 4];
            a2[k] = fmaf(xv.x, w0, a2[k]);
            a2[k] = fmaf(xv.y, w1, a2[k]);
            a2[k] = fmaf(xv.z, w2, a2[k]);
            a2[k] = fmaf(xv.w, w3, a2[k]);
        }
    }

    // ---- FC3: 16->1, relu; butterfly over 16-lane group, per element ----
    float w3v = sW3[u];
    float* outg = out + ebase + g;
#pragma unroll
    for (int k = 0; k < EPT; k++) {
        float p = tnha(a2[k]) * w3v;
#pragma unroll
        for (int off = 8; off; off >>= 1)
            p += __shfl_xor_sync(0xffffffffu, p, off, 16);
        if (u == 0) outg[2 * k] = fmaxf(p + sB3[0], 0.0f);
    }
}

extern "C" void kernel_launch(void* const* d_in, const int* in_sizes, int n_in,
                              void* d_out, int out_size)
{
    const float* mob  = (const float*)d_in[0];
    const float* ctrl = (const float*)d_in[1];
    const float* Wcc  = (const float*)d_in[3];
    const float* bcc  = (const float*)d_in[4];
    const float* Wih  = (const float*)d_in[5];
    const float* Whh  = (const float*)d_in[6];
    const float* bih  = (const float*)d_in[7];
    const float* bhh  = (const float*)d_in[8];
    const float* W1   = (const float*)d_in[9];
    const float* b1   = (const float*)d_in[10];
    const float* W2   = (const float*)d_in[11];
    const float* b2   = (const float*)d_in[12];
    const float* W3   = (const float*)d_in[13];
    const float* b3   = (const float*)d_in[14];

    int B = in_sizes[2];
    int blocks = (B + 2 * EPT * NW - 1) / (2 * EPT * NW);  // 32 elements per block

    infect_lstm_kernel<<<blocks, 128>>>(mob, ctrl, Wcc, bcc, Wih, Whh, bih, bhh,
                                        W1, b1, W2, b2, W3, b3, (float*)d_out);
}

// round 15
// speedup vs baseline: 14.8324x; 1.0233x over previous
#include <cuda_runtime.h>

// ---- hardware tanh (single MUFU op on sm_100) ----
__device__ __forceinline__ float tnha(float x) {
    float r; asm("tanh.approx.f32 %0, %1;" : "=f"(r) : "f"(x)); return r;
}
// sigmoid(x) = 0.5*tanh(x/2) + 0.5
__device__ __forceinline__ float siga(float x) {
    return fmaf(0.5f, tnha(0.5f * x), 0.5f);
}

#define NW 4   // warps per block
#define EPT 4  // elements per thread
#define NB 8   // batches per block (prologue amortization)
// Block = 128 threads = 4 warps; each warp handles 8 elements per batch,
// NB batches sequentially. Weights loaded to smem/registers ONCE per block.
__global__ void __launch_bounds__(128, 4) infect_lstm_kernel(
    const float* __restrict__ mob,   // [B,7]
    const float* __restrict__ ctrl,  // [B,5]
    const float* __restrict__ Wcc,   // [3,5]
    const float* __restrict__ bcc,   // [3]
    const float* __restrict__ Wih,   // [64,1]
    const float* __restrict__ Whh,   // [64,16]
    const float* __restrict__ bih,   // [64]
    const float* __restrict__ bhh,   // [64]
    const float* __restrict__ W1,    // [16,19]
    const float* __restrict__ b1,    // [16]
    const float* __restrict__ W2,    // [16,16]
    const float* __restrict__ b2,    // [16]
    const float* __restrict__ W3,    // [1,16]
    const float* __restrict__ b3,    // [1]
    float* __restrict__ out)         // [B]
{
    __shared__ __align__(16) float4 sWhhT[16 * 16]; // [m][u] -> (wi,wf,wg,wo)
    __shared__ __align__(16) float4 sWxB[16];       // [u] -> Wih per gate
    __shared__ __align__(16) float4 sBiasV[16];     // [u] -> bih+bhh per gate
    __shared__ float sW1T[19 * 16];                 // [i][u] = W1[u][i]
    __shared__ float sW2T[16 * 16];                 // [i][u] = W2[u][i]
    __shared__ float sW3[16], sB1[16], sB2[16];
    __shared__ float sWcc[15], sBcc[3], sB3[1];
    // h exchange: [slot][warp][elemLocal*16+u], 8 elements per warp, double-buffered
    __shared__ __align__(16) float sH[2][NW][128];

    const int tid = threadIdx.x;

    for (int i = tid; i < 256; i += 128) {
        int m = i >> 4, uu = i & 15;
        sWhhT[i] = make_float4(Whh[uu * 16 + m],
                               Whh[(16 + uu) * 16 + m],
                               Whh[(32 + uu) * 16 + m],
                               Whh[(48 + uu) * 16 + m]);
        sW2T[i] = W2[uu * 16 + m];   // [i=m][u]
    }
    for (int i = tid; i < 19 * 16; i += 128) {
        int col = i >> 4, uu = i & 15;
        sW1T[i] = W1[uu * 19 + col];
    }
    if (tid < 16) {
        int uu = tid;
        sWxB[uu]   = make_float4(Wih[uu], Wih[16 + uu], Wih[32 + uu], Wih[48 + uu]);
        sBiasV[uu] = make_float4(bih[uu]      + bhh[uu],
                                 bih[16 + uu] + bhh[16 + uu],
                                 bih[32 + uu] + bhh[32 + uu],
                                 bih[48 + uu] + bhh[48 + uu]);
        sW3[uu] = W3[uu]; sB1[uu] = b1[uu]; sB2[uu] = b2[uu];
    } else if (tid < 31) sWcc[tid - 16] = Wcc[tid - 16];
    else if (tid < 34) sBcc[tid - 31] = bcc[tid - 31];
    else if (tid == 34) sB3[0] = b3[0];
    __syncthreads();

    const int lane = tid & 31;
    const int u = lane & 15;
    const int g = lane >> 4;                 // lane group (0/1)
    const int w = tid >> 5;                  // warp id within block

    // ---- hoist this lane's Whh column set into registers (64 regs, shared) ----
    float4 wreg[16];
#pragma unroll
    for (int m = 0; m < 16; m++) wreg[m] = sWhhT[m * 16 + u];

    const float4 wx = sWxB[u];
    const float4 bb = sBiasV[u];

    // ---- batch loop: NB batches of 32 elements, weights stay resident ----
#pragma unroll 1
    for (int bi = 0; bi < NB; bi++) {
        const int ebase = ((blockIdx.x * NB + bi) * NW + w) * (2 * EPT);
        const float* mpg = mob  + (size_t)(ebase + g) * 7;   // element k at +14*k
        const float* cpg = ctrl + (size_t)(ebase + g) * 5;   // element k at +10*k

        __syncwarp();    // prior batch's sH[0] reads are done before reuse
        float cc[EPT];
#pragma unroll
        for (int k = 0; k < EPT; k++) {
            cc[k] = 0.0f;
            sH[0][w][(2 * k + g) * 16 + u] = 0.0f;
        }
        __syncwarp();

        // ---- LSTM: 7 steps, unrolled; four independent elements per thread ----
#pragma unroll
        for (int s = 0; s < 7; s++) {
            const int rp = s & 1, wp = rp ^ 1;
            float ai[EPT], af[EPT], ag[EPT], ao[EPT];
#pragma unroll
            for (int k = 0; k < EPT; k++) {
                float x = mpg[14 * k + s];
                ai[k] = fmaf(x, wx.x, bb.x);
                af[k] = fmaf(x, wx.y, bb.y);
                ag[k] = fmaf(x, wx.z, bb.z);
                ao[k] = fmaf(x, wx.w, bb.w);
            }
#pragma unroll
            for (int m4 = 0; m4 < 4; m4++) {
                const float4 w0 = wreg[m4 * 4 + 0];
                const float4 w1 = wreg[m4 * 4 + 1];
                const float4 w2 = wreg[m4 * 4 + 2];
                const float4 w3 = wreg[m4 * 4 + 3];
#pragma unroll
                for (int k = 0; k < EPT; k++) {
                    float4 hv = *(const float4*)&sH[rp][w][(2 * k + g) * 16 + m4 * 4];
                    ai[k] = fmaf(hv.x, w0.x, ai[k]);
                    af[k] = fmaf(hv.x, w0.y, af[k]);
                    ag[k] = fmaf(hv.x, w0.z, ag[k]);
                    ao[k] = fmaf(hv.x, w0.w, ao[k]);
                    ai[k] = fmaf(hv.y, w1.x, ai[k]);
                    af[k] = fmaf(hv.y, w1.y, af[k]);
                    ag[k] = fmaf(hv.y, w1.z, ag[k]);
                    ao[k] = fmaf(hv.y, w1.w, ao[k]);
                    ai[k] = fmaf(hv.z, w2.x, ai[k]);
                    af[k] = fmaf(hv.z, w2.y, af[k]);
                    ag[k] = fmaf(hv.z, w2.z, ag[k]);
                    ao[k] = fmaf(hv.z, w2.w, ao[k]);
                    ai[k] = fmaf(hv.w, w3.x, ai[k]);
                    af[k] = fmaf(hv.w, w3.y, af[k]);
                    ag[k] = fmaf(hv.w, w3.z, ag[k]);
                    ao[k] = fmaf(hv.w, w3.w, ao[k]);
                }
            }
#pragma unroll
            for (int k = 0; k < EPT; k++) {
                float ig = siga(ai[k]);
                float fg = siga(af[k]);
                float gg = tnha(ag[k]);
                float og = siga(ao[k]);
                cc[k] = fmaf(fg, cc[k], ig * gg);
                sH[wp][w][(2 * k + g) * 16 + u] = og * tnha(cc[k]);
            }
            __syncwarp();
        }
        // final h is in slot 1

        // ---- control heads ----
        float c0[EPT], c1[EPT], c2[EPT];
#pragma unroll
        for (int k = 0; k < EPT; k++) { c0[k] = sBcc[0]; c1[k] = sBcc[1]; c2[k] = sBcc[2]; }
#pragma unroll
        for (int i = 0; i < 5; i++) {
            float wa = sWcc[i], wb = sWcc[5 + i], wc = sWcc[10 + i];
#pragma unroll
            for (int k = 0; k < EPT; k++) {
                float v = cpg[10 * k + i];
                c0[k] = fmaf(v, wa, c0[k]);
                c1[k] = fmaf(v, wb, c1[k]);
                c2[k] = fmaf(v, wc, c2[k]);
            }
        }

        // ---- FC1: 19->16, tanh ----
        float a1[EPT];
#pragma unroll
        for (int k = 0; k < EPT; k++) a1[k] = sB1[u];
#pragma unroll
        for (int m4 = 0; m4 < 4; m4++) {
            float w0 = sW1T[(m4 * 4 + 0) * 16 + u];
            float w1 = sW1T[(m4 * 4 + 1) * 16 + u];
            float w2 = sW1T[(m4 * 4 + 2) * 16 + u];
            float w3 = sW1T[(m4 * 4 + 3) * 16 + u];
#pragma unroll
            for (int k = 0; k < EPT; k++) {
                float4 hv = *(const float4*)&sH[1][w][(2 * k + g) * 16 + m4 * 4];
                a1[k] = fmaf(hv.x, w0, a1[k]);
                a1[k] = fmaf(hv.y, w1, a1[k]);
                a1[k] = fmaf(hv.z, w2, a1[k]);
                a1[k] = fmaf(hv.w, w3, a1[k]);
            }
        }
        {
            float wc0 = sW1T[16 * 16 + u], wc1 = sW1T[17 * 16 + u], wc2 = sW1T[18 * 16 + u];
#pragma unroll
            for (int k = 0; k < EPT; k++) {
                a1[k] = fmaf(c0[k], wc0, a1[k]);
                a1[k] = fmaf(c1[k], wc1, a1[k]);
                a1[k] = fmaf(c2[k], wc2, a1[k]);
            }
        }
#pragma unroll
        for (int k = 0; k < EPT; k++) sH[0][w][(2 * k + g) * 16 + u] = tnha(a1[k]);
        __syncwarp();

        // ---- FC2: 16->16, tanh ----
        float a2[EPT];
#pragma unroll
        for (int k = 0; k < EPT; k++) a2[k] = sB2[u];
#pragma unroll
        for (int m4 = 0; m4 < 4; m4++) {
            float w0 = sW2T[(m4 * 4 + 0) * 16 + u];
            float w1 = sW2T[(m4 * 4 + 1) * 16 + u];
            float w2 = sW2T[(m4 * 4 + 2) * 16 + u];
            float w3 = sW2T[(m4 * 4 + 3) * 16 + u];
#pragma unroll
            for (int k = 0; k < EPT; k++) {
                float4 xv = *(const float4*)&sH[0][w][(2 * k + g) * 16 + m4 * 4];
                a2[k] = fmaf(xv.x, w0, a2[k]);
                a2[k] = fmaf(xv.y, w1, a2[k]);
                a2[k] = fmaf(xv.z, w2, a2[k]);
                a2[k] = fmaf(xv.w, w3, a2[k]);
            }
        }

        // ---- FC3: 16->1, relu; butterfly over 16-lane group, per element ----
        float w3v = sW3[u];
        float* outg = out + ebase + g;
#pragma unroll
        for (int k = 0; k < EPT; k++) {
            float p = tnha(a2[k]) * w3v;
#pragma unroll
            for (int off = 8; off; off >>= 1)
                p += __shfl_xor_sync(0xffffffffu, p, off, 16);
            if (u == 0) outg[2 * k] = fmaxf(p + sB3[0], 0.0f);
        }
    }
}

extern "C" void kernel_launch(void* const* d_in, const int* in_sizes, int n_in,
                              void* d_out, int out_size)
{
    const float* mob  = (const float*)d_in[0];
    const float* ctrl = (const float*)d_in[1];
    const float* Wcc  = (const float*)d_in[3];
    const float* bcc  = (const float*)d_in[4];
    const float* Wih  = (const float*)d_in[5];
    const float* Whh  = (const float*)d_in[6];
    const float* bih  = (const float*)d_in[7];
    const float* bhh  = (const float*)d_in[8];
    const float* W1   = (const float*)d_in[9];
    const float* b1   = (const float*)d_in[10];
    const float* W2   = (const float*)d_in[11];
    const float* b2   = (const float*)d_in[12];
    const float* W3   = (const float*)d_in[13];
    const float* b3   = (const float*)d_in[14];

    int B = in_sizes[2];
    int per_block = 2 * EPT * NW * NB;                 // 256 elements per block
    int blocks = (B + per_block - 1) / per_block;      // 4096 for B=1M

    infect_lstm_kernel<<<blocks, 128>>>(mob, ctrl, Wcc, bcc, Wih, Whh, bih, bhh,
                                        W1, b1, W2, b2, W3, b3, (float*)d_out);
}